// round 1
// baseline (speedup 1.0000x reference)
#include <cuda_runtime.h>
#include <cstdint>

// Problem constants
#define B_   4
#define N_   1024
#define D_   1024
#define H_   16
#define DH_  64
#define M_   (B_ * N_)    // 4096 rows for projection GEMMs
#define BH_  (B_ * H_)    // 64 (batch*heads)

// Scratch (allocation-free rule: __device__ globals)
__device__ float g_q[(size_t)BH_ * N_ * DH_];     // [b,h,n,dh]
__device__ float g_k[(size_t)BH_ * N_ * DH_];
__device__ float g_v[(size_t)BH_ * N_ * DH_];
__device__ float g_attn[(size_t)M_ * D_];         // [b,n,d] combined heads
__device__ int   g_mask4;                          // 1 = 4-byte mask elems, 0 = 1-byte

// ---------------------------------------------------------------------------
// Mask dtype detection: scan 64KB. Any byte>1 -> 4-byte (f32/i32, test word!=0).
// Else any nonzero byte at offset%4!=0 -> 1-byte (bool/u8). Else 4-byte.
// ---------------------------------------------------------------------------
__global__ void detect_mask_kind(const unsigned char* __restrict__ m) {
    __shared__ int has_gt1, has_mis;
    if (threadIdx.x == 0) { has_gt1 = 0; has_mis = 0; }
    __syncthreads();
    int lg = 0, lm = 0;
    for (int i = threadIdx.x * 16; i < 65536; i += blockDim.x * 16) {
        uint4 v = *(const uint4*)(m + i);
        unsigned int w[4] = {v.x, v.y, v.z, v.w};
#pragma unroll
        for (int j = 0; j < 4; j++) {
#pragma unroll
            for (int b = 0; b < 4; b++) {
                unsigned int byte = (w[j] >> (8 * b)) & 0xFFu;
                int pos = i + j * 4 + b;
                if (byte > 1u) lg = 1;
                if (byte != 0u && (pos & 3)) lm = 1;
            }
        }
    }
    if (lg) atomicOr(&has_gt1, 1);
    if (lm) atomicOr(&has_mis, 1);
    __syncthreads();
    if (threadIdx.x == 0) g_mask4 = (has_gt1 || !has_mis) ? 1 : 0;
}

// ---------------------------------------------------------------------------
// NT SGEMM: C[M x D_] = A[M x D_] @ W[D_ x D_]^T + bias  (K = D_)
// MODE 0: plain row-major output. MODE 1: head-split output [b,h,n,dh].
// 64x64 tile, BK=16, 256 threads, 4x4 microtile per thread.
// ---------------------------------------------------------------------------
template <int MODE>
__global__ void __launch_bounds__(256) gemm_nt(const float* __restrict__ A,
                                               const float* __restrict__ W,
                                               const float* __restrict__ bias,
                                               float* __restrict__ C) {
    __shared__ float As[16][65];
    __shared__ float Bs[16][65];
    const int tid = threadIdx.x;
    const int tx = tid & 15, ty = tid >> 4;
    const int row0 = blockIdx.y * 64, col0 = blockIdx.x * 64;
    const int lr = tid >> 2;          // 0..63
    const int lc = (tid & 3) * 4;     // 0,4,8,12

    float acc[4][4] = {};
    for (int k0 = 0; k0 < D_; k0 += 16) {
        float4 a = *(const float4*)&A[(size_t)(row0 + lr) * D_ + k0 + lc];
        float4 b = *(const float4*)&W[(size_t)(col0 + lr) * D_ + k0 + lc];
        As[lc + 0][lr] = a.x; As[lc + 1][lr] = a.y; As[lc + 2][lr] = a.z; As[lc + 3][lr] = a.w;
        Bs[lc + 0][lr] = b.x; Bs[lc + 1][lr] = b.y; Bs[lc + 2][lr] = b.z; Bs[lc + 3][lr] = b.w;
        __syncthreads();
#pragma unroll
        for (int kk = 0; kk < 16; kk++) {
            float av[4], bv[4];
#pragma unroll
            for (int i = 0; i < 4; i++) av[i] = As[kk][ty * 4 + i];
#pragma unroll
            for (int j = 0; j < 4; j++) bv[j] = Bs[kk][tx * 4 + j];
#pragma unroll
            for (int i = 0; i < 4; i++)
#pragma unroll
                for (int j = 0; j < 4; j++) acc[i][j] = fmaf(av[i], bv[j], acc[i][j]);
        }
        __syncthreads();
    }
#pragma unroll
    for (int i = 0; i < 4; i++) {
        const int row = row0 + ty * 4 + i;
#pragma unroll
        for (int j = 0; j < 4; j++) {
            const int col = col0 + tx * 4 + j;
            const float val = acc[i][j] + bias[col];
            if (MODE == 0) {
                C[(size_t)row * D_ + col] = val;
            } else {
                const int b = row >> 10;      // row / N_
                const int n = row & (N_ - 1);
                const int h = col >> 6;       // col / DH_
                const int dh = col & (DH_ - 1);
                C[(((size_t)b * H_ + h) * N_ + n) * DH_ + dh] = val;
            }
        }
    }
}

// ---------------------------------------------------------------------------
// Scores: S[bh][n][m] = (q[bh,n,:] . k[bh,m,:]) / 8, masked -> -1e10.
// 64x64 tile per block, full K=64 in smem.
// ---------------------------------------------------------------------------
__global__ void __launch_bounds__(256) scores_kernel(const unsigned char* __restrict__ maskp,
                                                     float* __restrict__ wout) {
    __shared__ float Qs[64][65];
    __shared__ float Ks[64][65];
    const int bh = blockIdx.z;
    const int row0 = blockIdx.y * 64;   // n
    const int col0 = blockIdx.x * 64;   // m
    const int tid = threadIdx.x;
    const int tx = tid & 15, ty = tid >> 4;
    const float* qb = g_q + (size_t)bh * N_ * DH_;
    const float* kb = g_k + (size_t)bh * N_ * DH_;

    for (int l = tid; l < 64 * 16; l += 256) {
        const int r = l >> 4;
        const int c = (l & 15) << 2;
        float4 a = *(const float4*)&qb[(size_t)(row0 + r) * DH_ + c];
        Qs[r][c] = a.x; Qs[r][c + 1] = a.y; Qs[r][c + 2] = a.z; Qs[r][c + 3] = a.w;
        float4 b = *(const float4*)&kb[(size_t)(col0 + r) * DH_ + c];
        Ks[r][c] = b.x; Ks[r][c + 1] = b.y; Ks[r][c + 2] = b.z; Ks[r][c + 3] = b.w;
    }
    __syncthreads();

    float acc[4][4] = {};
#pragma unroll
    for (int kk = 0; kk < 64; kk++) {
        float av[4], bv[4];
#pragma unroll
        for (int i = 0; i < 4; i++) av[i] = Qs[ty * 4 + i][kk];
#pragma unroll
        for (int j = 0; j < 4; j++) bv[j] = Ks[tx * 4 + j][kk];
#pragma unroll
        for (int i = 0; i < 4; i++)
#pragma unroll
            for (int j = 0; j < 4; j++) acc[i][j] = fmaf(av[i], bv[j], acc[i][j]);
    }

    const int m4 = g_mask4;
    const unsigned int* mask32 = (const unsigned int*)maskp;
#pragma unroll
    for (int i = 0; i < 4; i++) {
        const int r = row0 + ty * 4 + i;
#pragma unroll
        for (int j = 0; j < 4; j++) {
            const int c = col0 + tx * 4 + j;
            const size_t idx = ((size_t)bh * N_ + r) * N_ + c;
            const bool masked = m4 ? (mask32[idx] != 0u) : (maskp[idx] != 0);
            wout[idx] = masked ? -1e10f : acc[i][j] * 0.125f;
        }
    }
}

// ---------------------------------------------------------------------------
// In-place row softmax over weights: BH_*N_ rows of N_ = 1024 elements.
// 256 threads, one float4 per thread.
// ---------------------------------------------------------------------------
__global__ void __launch_bounds__(256) softmax_rows(float* __restrict__ w) {
    float* p = w + (size_t)blockIdx.x * N_;
    float4 v = ((float4*)p)[threadIdx.x];

    __shared__ float smax[8];
    __shared__ float ssum[8];
    const int warp = threadIdx.x >> 5, lane = threadIdx.x & 31;

    float m = fmaxf(fmaxf(v.x, v.y), fmaxf(v.z, v.w));
#pragma unroll
    for (int o = 16; o; o >>= 1) m = fmaxf(m, __shfl_xor_sync(~0u, m, o));
    if (lane == 0) smax[warp] = m;
    __syncthreads();
    if (warp == 0) {
        float t = (lane < 8) ? smax[lane] : -3.4e38f;
#pragma unroll
        for (int o = 4; o; o >>= 1) t = fmaxf(t, __shfl_xor_sync(~0u, t, o));
        if (lane == 0) smax[0] = t;
    }
    __syncthreads();
    m = smax[0];

    v.x = __expf(v.x - m); v.y = __expf(v.y - m);
    v.z = __expf(v.z - m); v.w = __expf(v.w - m);
    float s = v.x + v.y + v.z + v.w;
#pragma unroll
    for (int o = 16; o; o >>= 1) s += __shfl_xor_sync(~0u, s, o);
    if (lane == 0) ssum[warp] = s;
    __syncthreads();
    if (warp == 0) {
        float t = (lane < 8) ? ssum[lane] : 0.0f;
#pragma unroll
        for (int o = 4; o; o >>= 1) t += __shfl_xor_sync(~0u, t, o);
        if (lane == 0) ssum[0] = t;
    }
    __syncthreads();
    const float inv = 1.0f / ssum[0];
    v.x *= inv; v.y *= inv; v.z *= inv; v.w *= inv;
    ((float4*)p)[threadIdx.x] = v;
}

// ---------------------------------------------------------------------------
// attn[bh][n][dh] = sum_m weights[bh][n][m] * v[bh][m][dh]; write to [b,n,d].
// BM=64, BN=64 (full DH), BK=32.
// ---------------------------------------------------------------------------
__global__ void __launch_bounds__(256) attn_kernel(const float* __restrict__ w) {
    __shared__ float Ws[64][33];
    __shared__ float Vs[32][65];
    const int bh = blockIdx.y;
    const int row0 = blockIdx.x * 64;
    const int tid = threadIdx.x;
    const int tx = tid & 15, ty = tid >> 4;
    const float* wb = w + (size_t)bh * N_ * N_;
    const float* vb = g_v + (size_t)bh * N_ * DH_;

    float acc[4][4] = {};
    for (int k0 = 0; k0 < N_; k0 += 32) {
        for (int l = tid; l < 512; l += 256) {
            const int r = l >> 3;
            const int c = (l & 7) << 2;
            float4 a = *(const float4*)&wb[(size_t)(row0 + r) * N_ + k0 + c];
            Ws[r][c] = a.x; Ws[r][c + 1] = a.y; Ws[r][c + 2] = a.z; Ws[r][c + 3] = a.w;
        }
        for (int l = tid; l < 512; l += 256) {
            const int r = l >> 4;
            const int c = (l & 15) << 2;
            float4 b = *(const float4*)&vb[(size_t)(k0 + r) * DH_ + c];
            Vs[r][c] = b.x; Vs[r][c + 1] = b.y; Vs[r][c + 2] = b.z; Vs[r][c + 3] = b.w;
        }
        __syncthreads();
#pragma unroll
        for (int kk = 0; kk < 32; kk++) {
            float av[4], bv[4];
#pragma unroll
            for (int i = 0; i < 4; i++) av[i] = Ws[ty * 4 + i][kk];
#pragma unroll
            for (int j = 0; j < 4; j++) bv[j] = Vs[kk][tx * 4 + j];
#pragma unroll
            for (int i = 0; i < 4; i++)
#pragma unroll
                for (int j = 0; j < 4; j++) acc[i][j] = fmaf(av[i], bv[j], acc[i][j]);
        }
        __syncthreads();
    }

    const int b = bh >> 4;         // bh / H_
    const int h = bh & (H_ - 1);
#pragma unroll
    for (int i = 0; i < 4; i++) {
        const int n = row0 + ty * 4 + i;
#pragma unroll
        for (int j = 0; j < 4; j++) {
            const int dh = tx * 4 + j;
            g_attn[((size_t)b * N_ + n) * D_ + h * DH_ + dh] = acc[i][j];
        }
    }
}

// ---------------------------------------------------------------------------
extern "C" void kernel_launch(void* const* d_in, const int* in_sizes, int n_in,
                              void* d_out, int out_size) {
    const float* Q  = (const float*)d_in[0];
    const float* K  = (const float*)d_in[1];
    const float* V  = (const float*)d_in[2];
    const unsigned char* mask = (const unsigned char*)d_in[3];
    const float* Wq = (const float*)d_in[4];
    const float* bq = (const float*)d_in[5];
    const float* Wk = (const float*)d_in[6];
    const float* bk = (const float*)d_in[7];
    const float* Wv = (const float*)d_in[8];
    const float* bv = (const float*)d_in[9];
    const float* Wo = (const float*)d_in[10];
    const float* bo = (const float*)d_in[11];

    float* xout = (float*)d_out;                       // [B, N, D]
    float* wout = xout + (size_t)M_ * D_;              // [B, H, N, N]

    float *qp, *kp, *vp, *ap;
    cudaGetSymbolAddress((void**)&qp, g_q);
    cudaGetSymbolAddress((void**)&kp, g_k);
    cudaGetSymbolAddress((void**)&vp, g_v);
    cudaGetSymbolAddress((void**)&ap, g_attn);

    detect_mask_kind<<<1, 256>>>(mask);

    dim3 gp(D_ / 64, M_ / 64);                         // (16, 64)
    gemm_nt<1><<<gp, 256>>>(Q, Wq, bq, qp);
    gemm_nt<1><<<gp, 256>>>(K, Wk, bk, kp);
    gemm_nt<1><<<gp, 256>>>(V, Wv, bv, vp);

    scores_kernel<<<dim3(N_ / 64, N_ / 64, BH_), 256>>>(mask, wout);
    softmax_rows<<<BH_ * N_, 256>>>(wout);
    attn_kernel<<<dim3(N_ / 64, BH_), 256>>>(wout);

    gemm_nt<0><<<gp, 256>>>(ap, Wo, bo, xout);
}

// round 3
// speedup vs baseline: 1.6760x; 1.6760x over previous
#include <cuda_runtime.h>
#include <cuda_bf16.h>
#include <cstdint>

// Problem constants
#define B_   4
#define N_   1024
#define D_   1024
#define H_   16
#define DH_  64
#define M_   (B_ * N_)    // 4096
#define BH_  (B_ * H_)    // 64

// Scratch (allocation-free rule: __device__ globals)
__device__ float g_q[(size_t)BH_ * N_ * DH_];
__device__ float g_k[(size_t)BH_ * N_ * DH_];
__device__ float g_v[(size_t)BH_ * N_ * DH_];
__device__ float g_attn[(size_t)M_ * D_];
__device__ int   g_mask4;

// ===========================================================================
// Generic-PTX tensor-core helpers (sm_80+ instructions only; no 'a' features)
// ===========================================================================
__device__ __forceinline__ uint32_t smem_u32(const void* p) {
    uint32_t a;
    asm("{ .reg .u64 t; cvta.to.shared.u64 t, %1; cvt.u32.u64 %0, t; }" : "=r"(a) : "l"(p));
    return a;
}
__device__ __forceinline__ void ldsm_x4(uint32_t* r, uint32_t addr) {
    asm volatile("ldmatrix.sync.aligned.m8n8.x4.shared.b16 {%0,%1,%2,%3}, [%4];"
                 : "=r"(r[0]), "=r"(r[1]), "=r"(r[2]), "=r"(r[3]) : "r"(addr));
}
__device__ __forceinline__ void mma_bf16(float* c, const uint32_t* a, const uint32_t* b) {
    asm volatile(
        "mma.sync.aligned.m16n8k16.row.col.f32.bf16.bf16.f32 "
        "{%0,%1,%2,%3}, {%4,%5,%6,%7}, {%8,%9}, {%0,%1,%2,%3};"
        : "+f"(c[0]), "+f"(c[1]), "+f"(c[2]), "+f"(c[3])
        : "r"(a[0]), "r"(a[1]), "r"(a[2]), "r"(a[3]), "r"(b[0]), "r"(b[1]));
}
__device__ __forceinline__ void cvt_pair(float x0, float x1, uint32_t& hi, uint32_t& lo) {
    __nv_bfloat16 h0 = __float2bfloat16(x0);
    __nv_bfloat16 h1 = __float2bfloat16(x1);
    __nv_bfloat16 l0 = __float2bfloat16(x0 - __bfloat162float(h0));
    __nv_bfloat16 l1 = __float2bfloat16(x1 - __bfloat162float(h1));
    hi = ((uint32_t)__bfloat16_as_ushort(h1) << 16) | (uint32_t)__bfloat16_as_ushort(h0);
    lo = ((uint32_t)__bfloat16_as_ushort(l1) << 16) | (uint32_t)__bfloat16_as_ushort(l0);
}

// ===========================================================================
// bf16x3 NT GEMM via mma.sync: C[4096 x 1024] = A @ W^T + bias, K = 1024.
// CTA 128x128, BK=32, 8 warps (2x4), warp tile 64x32, double-buffered smem.
// Smem rows padded to 40 bf16 (80B) -> conflict-free ldmatrix.
// MODE 0: row-major out. MODE 1: head-split out [b,h,n,dh].
// ===========================================================================
#define BK_      32
#define LDS_     40                         // bf16 elems per padded row
#define TILE_B   (128 * LDS_ * 2)           // 10240 bytes per tile
#define BUF_B    (4 * TILE_B)               // Ahi, Alo, Bhi, Blo
#define NUM_KB   (D_ / BK_)                 // 32

template <int MODE>
__global__ void __launch_bounds__(256, 1) gemm_mma(const float* __restrict__ A,
                                                   const float* __restrict__ W,
                                                   const float* __restrict__ bias,
                                                   float* __restrict__ C) {
    extern __shared__ char smem[];
    __shared__ float s_bias[128];

    const int tid = threadIdx.x;
    const int wid = tid >> 5;
    const int lane = tid & 31;
    const int warp_m = wid >> 2;      // 0..1
    const int warp_n = wid & 3;       // 0..3
    const int row0 = blockIdx.y * 128;
    const int col0 = blockIdx.x * 128;

    if (tid < 128) s_bias[tid] = bias[col0 + tid];

    // gmem load mapping: each thread: 1 row, 16 contiguous floats (A and B)
    const int r  = tid >> 1;
    const int ch = (tid & 1) * 16;
    const float* Ap = A + (size_t)(row0 + r) * D_ + ch;
    const float* Bp = W + (size_t)(col0 + r) * D_ + ch;
    const uint32_t st_off = (uint32_t)r * (LDS_ * 2) + (uint32_t)ch * 2; // bytes in tile

    const uint32_t sb = smem_u32(smem);

    // ldmatrix lane addressing (constant per thread)
    const int seg = lane >> 3, l7 = lane & 7;
    const int a_row = warp_m * 64 + (seg & 1) * 8 + l7;       // + mt*16
    const int a_colb = (((seg >> 1) & 1) * 8) * 2;            // byte, + s*32
    const int b_row = warp_n * 32 + ((seg >> 1) & 1) * 8 + l7; // + p*16
    const int b_colb = ((seg & 1) * 8) * 2;                   // byte, + s*32

    float acc[4][4][4] = {};
    float fa[16], fb[16];

    // prologue: load k-block 0, convert, store buffer 0
#pragma unroll
    for (int j = 0; j < 4; j++) {
        *(float4*)(fa + j * 4) = *(const float4*)(Ap + j * 4);
        *(float4*)(fb + j * 4) = *(const float4*)(Bp + j * 4);
    }
    {
        uint4 ah[2], al[2], bh[2], bl[2];
#pragma unroll
        for (int j = 0; j < 2; j++) {
            cvt_pair(fa[j*8+0], fa[j*8+1], ah[j].x, al[j].x);
            cvt_pair(fa[j*8+2], fa[j*8+3], ah[j].y, al[j].y);
            cvt_pair(fa[j*8+4], fa[j*8+5], ah[j].z, al[j].z);
            cvt_pair(fa[j*8+6], fa[j*8+7], ah[j].w, al[j].w);
            cvt_pair(fb[j*8+0], fb[j*8+1], bh[j].x, bl[j].x);
            cvt_pair(fb[j*8+2], fb[j*8+3], bh[j].y, bl[j].y);
            cvt_pair(fb[j*8+4], fb[j*8+5], bh[j].z, bl[j].z);
            cvt_pair(fb[j*8+6], fb[j*8+7], bh[j].w, bl[j].w);
        }
        char* base = smem;
#pragma unroll
        for (int j = 0; j < 2; j++) {
            *(uint4*)(base + 0*TILE_B + st_off + j*16) = ah[j];
            *(uint4*)(base + 1*TILE_B + st_off + j*16) = al[j];
            *(uint4*)(base + 2*TILE_B + st_off + j*16) = bh[j];
            *(uint4*)(base + 3*TILE_B + st_off + j*16) = bl[j];
        }
    }
    __syncthreads();

    for (int kb = 0; kb < NUM_KB; kb++) {
        // prefetch next k-block into regs
        if (kb + 1 < NUM_KB) {
            const int k0 = (kb + 1) * BK_;
#pragma unroll
            for (int j = 0; j < 4; j++) {
                *(float4*)(fa + j * 4) = *(const float4*)(Ap + k0 + j * 4);
                *(float4*)(fb + j * 4) = *(const float4*)(Bp + k0 + j * 4);
            }
        }

        // compute 2 k16-steps from current buffer
        const uint32_t buf = sb + (uint32_t)(kb & 1) * BUF_B;
#pragma unroll
        for (int s = 0; s < 2; s++) {
            uint32_t a_hi[4][4], a_lo[4][4], b_hi[4][2], b_lo[4][2];
#pragma unroll
            for (int mt = 0; mt < 4; mt++) {
                const uint32_t off = (uint32_t)(a_row + mt * 16) * (LDS_ * 2) + a_colb + s * 32;
                ldsm_x4(a_hi[mt], buf + 0 * TILE_B + off);
                ldsm_x4(a_lo[mt], buf + 1 * TILE_B + off);
            }
#pragma unroll
            for (int p = 0; p < 2; p++) {
                const uint32_t off = (uint32_t)(b_row + p * 16) * (LDS_ * 2) + b_colb + s * 32;
                uint32_t th[4], tl[4];
                ldsm_x4(th, buf + 2 * TILE_B + off);
                ldsm_x4(tl, buf + 3 * TILE_B + off);
                b_hi[2*p][0] = th[0]; b_hi[2*p][1] = th[1];
                b_hi[2*p+1][0] = th[2]; b_hi[2*p+1][1] = th[3];
                b_lo[2*p][0] = tl[0]; b_lo[2*p][1] = tl[1];
                b_lo[2*p+1][0] = tl[2]; b_lo[2*p+1][1] = tl[3];
            }
#pragma unroll
            for (int mt = 0; mt < 4; mt++)
#pragma unroll
                for (int nt = 0; nt < 4; nt++) {
                    mma_bf16(acc[mt][nt], a_hi[mt], b_hi[nt]);
                    mma_bf16(acc[mt][nt], a_lo[mt], b_hi[nt]);
                    mma_bf16(acc[mt][nt], a_hi[mt], b_lo[nt]);
                }
        }

        // convert + store prefetched block into other buffer
        if (kb + 1 < NUM_KB) {
            uint4 ah[2], al[2], bh[2], bl[2];
#pragma unroll
            for (int j = 0; j < 2; j++) {
                cvt_pair(fa[j*8+0], fa[j*8+1], ah[j].x, al[j].x);
                cvt_pair(fa[j*8+2], fa[j*8+3], ah[j].y, al[j].y);
                cvt_pair(fa[j*8+4], fa[j*8+5], ah[j].z, al[j].z);
                cvt_pair(fa[j*8+6], fa[j*8+7], ah[j].w, al[j].w);
                cvt_pair(fb[j*8+0], fb[j*8+1], bh[j].x, bl[j].x);
                cvt_pair(fb[j*8+2], fb[j*8+3], bh[j].y, bl[j].y);
                cvt_pair(fb[j*8+4], fb[j*8+5], bh[j].z, bl[j].z);
                cvt_pair(fb[j*8+6], fb[j*8+7], bh[j].w, bl[j].w);
            }
            char* base = smem + ((kb + 1) & 1) * BUF_B;
#pragma unroll
            for (int j = 0; j < 2; j++) {
                *(uint4*)(base + 0*TILE_B + st_off + j*16) = ah[j];
                *(uint4*)(base + 1*TILE_B + st_off + j*16) = al[j];
                *(uint4*)(base + 2*TILE_B + st_off + j*16) = bh[j];
                *(uint4*)(base + 3*TILE_B + st_off + j*16) = bl[j];
            }
        }
        __syncthreads();
    }

    // epilogue
    const int group = lane >> 2, tg = lane & 3;
#pragma unroll
    for (int mt = 0; mt < 4; mt++) {
#pragma unroll
        for (int nt = 0; nt < 4; nt++) {
#pragma unroll
            for (int rg = 0; rg < 4; rg++) {
                const int row = row0 + warp_m * 64 + mt * 16 + group + (rg >> 1) * 8;
                const int lcol = warp_n * 32 + nt * 8 + tg * 2 + (rg & 1);
                const int col = col0 + lcol;
                const float val = acc[mt][nt][rg] + s_bias[lcol];
                if (MODE == 0) {
                    C[(size_t)row * D_ + col] = val;
                } else {
                    const int b = row >> 10;
                    const int n = row & (N_ - 1);
                    const int h = col >> 6;
                    const int dh = col & (DH_ - 1);
                    C[(((size_t)b * H_ + h) * N_ + n) * DH_ + dh] = val;
                }
            }
        }
    }
}

// ===========================================================================
// Mask dtype detection (unchanged)
// ===========================================================================
__global__ void detect_mask_kind(const unsigned char* __restrict__ m) {
    __shared__ int has_gt1, has_mis;
    if (threadIdx.x == 0) { has_gt1 = 0; has_mis = 0; }
    __syncthreads();
    int lg = 0, lm = 0;
    for (int i = threadIdx.x * 16; i < 65536; i += blockDim.x * 16) {
        uint4 v = *(const uint4*)(m + i);
        unsigned int w[4] = {v.x, v.y, v.z, v.w};
#pragma unroll
        for (int j = 0; j < 4; j++) {
#pragma unroll
            for (int b = 0; b < 4; b++) {
                unsigned int byte = (w[j] >> (8 * b)) & 0xFFu;
                int pos = i + j * 4 + b;
                if (byte > 1u) lg = 1;
                if (byte != 0u && (pos & 3)) lm = 1;
            }
        }
    }
    if (lg) atomicOr(&has_gt1, 1);
    if (lm) atomicOr(&has_mis, 1);
    __syncthreads();
    if (threadIdx.x == 0) g_mask4 = (has_gt1 || !has_mis) ? 1 : 0;
}

// ===========================================================================
// Scores (fp32, unchanged this round)
// ===========================================================================
__global__ void __launch_bounds__(256) scores_kernel(const unsigned char* __restrict__ maskp,
                                                     float* __restrict__ wout) {
    __shared__ float Qs[64][65];
    __shared__ float Ks[64][65];
    const int bh = blockIdx.z;
    const int row0 = blockIdx.y * 64;
    const int col0 = blockIdx.x * 64;
    const int tid = threadIdx.x;
    const int tx = tid & 15, ty = tid >> 4;
    const float* qb = g_q + (size_t)bh * N_ * DH_;
    const float* kb = g_k + (size_t)bh * N_ * DH_;

    for (int l = tid; l < 64 * 16; l += 256) {
        const int rr = l >> 4;
        const int cc = (l & 15) << 2;
        float4 a = *(const float4*)&qb[(size_t)(row0 + rr) * DH_ + cc];
        Qs[rr][cc] = a.x; Qs[rr][cc + 1] = a.y; Qs[rr][cc + 2] = a.z; Qs[rr][cc + 3] = a.w;
        float4 b = *(const float4*)&kb[(size_t)(col0 + rr) * DH_ + cc];
        Ks[rr][cc] = b.x; Ks[rr][cc + 1] = b.y; Ks[rr][cc + 2] = b.z; Ks[rr][cc + 3] = b.w;
    }
    __syncthreads();

    float acc[4][4] = {};
#pragma unroll
    for (int kk = 0; kk < 64; kk++) {
        float av[4], bv[4];
#pragma unroll
        for (int i = 0; i < 4; i++) av[i] = Qs[ty * 4 + i][kk];
#pragma unroll
        for (int j = 0; j < 4; j++) bv[j] = Ks[tx * 4 + j][kk];
#pragma unroll
        for (int i = 0; i < 4; i++)
#pragma unroll
            for (int j = 0; j < 4; j++) acc[i][j] = fmaf(av[i], bv[j], acc[i][j]);
    }

    const int m4 = g_mask4;
    const unsigned int* mask32 = (const unsigned int*)maskp;
#pragma unroll
    for (int i = 0; i < 4; i++) {
        const int rr = row0 + ty * 4 + i;
#pragma unroll
        for (int j = 0; j < 4; j++) {
            const int cc = col0 + tx * 4 + j;
            const size_t idx = ((size_t)bh * N_ + rr) * N_ + cc;
            const bool masked = m4 ? (mask32[idx] != 0u) : (maskp[idx] != 0);
            wout[idx] = masked ? -1e10f : acc[i][j] * 0.125f;
        }
    }
}

// ===========================================================================
// Row softmax (unchanged)
// ===========================================================================
__global__ void __launch_bounds__(256) softmax_rows(float* __restrict__ w) {
    float* p = w + (size_t)blockIdx.x * N_;
    float4 v = ((float4*)p)[threadIdx.x];

    __shared__ float smax[8];
    __shared__ float ssum[8];
    const int warp = threadIdx.x >> 5, lane = threadIdx.x & 31;

    float m = fmaxf(fmaxf(v.x, v.y), fmaxf(v.z, v.w));
#pragma unroll
    for (int o = 16; o; o >>= 1) m = fmaxf(m, __shfl_xor_sync(~0u, m, o));
    if (lane == 0) smax[warp] = m;
    __syncthreads();
    if (warp == 0) {
        float t = (lane < 8) ? smax[lane] : -3.4e38f;
#pragma unroll
        for (int o = 4; o; o >>= 1) t = fmaxf(t, __shfl_xor_sync(~0u, t, o));
        if (lane == 0) smax[0] = t;
    }
    __syncthreads();
    m = smax[0];

    v.x = __expf(v.x - m); v.y = __expf(v.y - m);
    v.z = __expf(v.z - m); v.w = __expf(v.w - m);
    float s = v.x + v.y + v.z + v.w;
#pragma unroll
    for (int o = 16; o; o >>= 1) s += __shfl_xor_sync(~0u, s, o);
    if (lane == 0) ssum[warp] = s;
    __syncthreads();
    if (warp == 0) {
        float t = (lane < 8) ? ssum[lane] : 0.0f;
#pragma unroll
        for (int o = 4; o; o >>= 1) t += __shfl_xor_sync(~0u, t, o);
        if (lane == 0) ssum[0] = t;
    }
    __syncthreads();
    const float inv = 1.0f / ssum[0];
    v.x *= inv; v.y *= inv; v.z *= inv; v.w *= inv;
    ((float4*)p)[threadIdx.x] = v;
}

// ===========================================================================
// attn = weights @ v (fp32, unchanged this round)
// ===========================================================================
__global__ void __launch_bounds__(256) attn_kernel(const float* __restrict__ w) {
    __shared__ float Ws[64][33];
    __shared__ float Vs[32][65];
    const int bh = blockIdx.y;
    const int row0 = blockIdx.x * 64;
    const int tid = threadIdx.x;
    const int tx = tid & 15, ty = tid >> 4;
    const float* wb = w + (size_t)bh * N_ * N_;
    const float* vb = g_v + (size_t)bh * N_ * DH_;

    float acc[4][4] = {};
    for (int k0 = 0; k0 < N_; k0 += 32) {
        for (int l = tid; l < 512; l += 256) {
            const int rr = l >> 3;
            const int cc = (l & 7) << 2;
            float4 a = *(const float4*)&wb[(size_t)(row0 + rr) * N_ + k0 + cc];
            Ws[rr][cc] = a.x; Ws[rr][cc + 1] = a.y; Ws[rr][cc + 2] = a.z; Ws[rr][cc + 3] = a.w;
        }
        for (int l = tid; l < 512; l += 256) {
            const int rr = l >> 4;
            const int cc = (l & 15) << 2;
            float4 b = *(const float4*)&vb[(size_t)(k0 + rr) * DH_ + cc];
            Vs[rr][cc] = b.x; Vs[rr][cc + 1] = b.y; Vs[rr][cc + 2] = b.z; Vs[rr][cc + 3] = b.w;
        }
        __syncthreads();
#pragma unroll
        for (int kk = 0; kk < 32; kk++) {
            float av[4], bv[4];
#pragma unroll
            for (int i = 0; i < 4; i++) av[i] = Ws[ty * 4 + i][kk];
#pragma unroll
            for (int j = 0; j < 4; j++) bv[j] = Vs[kk][tx * 4 + j];
#pragma unroll
            for (int i = 0; i < 4; i++)
#pragma unroll
                for (int j = 0; j < 4; j++) acc[i][j] = fmaf(av[i], bv[j], acc[i][j]);
        }
        __syncthreads();
    }

    const int b = bh >> 4;
    const int h = bh & (H_ - 1);
#pragma unroll
    for (int i = 0; i < 4; i++) {
        const int n = row0 + ty * 4 + i;
#pragma unroll
        for (int j = 0; j < 4; j++) {
            const int dh = tx * 4 + j;
            g_attn[((size_t)b * N_ + n) * D_ + h * DH_ + dh] = acc[i][j];
        }
    }
}

// ===========================================================================
extern "C" void kernel_launch(void* const* d_in, const int* in_sizes, int n_in,
                              void* d_out, int out_size) {
    const float* Q  = (const float*)d_in[0];
    const float* K  = (const float*)d_in[1];
    const float* V  = (const float*)d_in[2];
    const unsigned char* mask = (const unsigned char*)d_in[3];
    const float* Wq = (const float*)d_in[4];
    const float* bq = (const float*)d_in[5];
    const float* Wk = (const float*)d_in[6];
    const float* bk = (const float*)d_in[7];
    const float* Wv = (const float*)d_in[8];
    const float* bv = (const float*)d_in[9];
    const float* Wo = (const float*)d_in[10];
    const float* bo = (const float*)d_in[11];

    float* xout = (float*)d_out;
    float* wout = xout + (size_t)M_ * D_;

    float *qp, *kp, *vp, *ap;
    cudaGetSymbolAddress((void**)&qp, g_q);
    cudaGetSymbolAddress((void**)&kp, g_k);
    cudaGetSymbolAddress((void**)&vp, g_v);
    cudaGetSymbolAddress((void**)&ap, g_attn);

    const int smem_bytes = 2 * BUF_B;   // 81920
    cudaFuncSetAttribute(gemm_mma<0>, cudaFuncAttributeMaxDynamicSharedMemorySize, smem_bytes);
    cudaFuncSetAttribute(gemm_mma<1>, cudaFuncAttributeMaxDynamicSharedMemorySize, smem_bytes);

    detect_mask_kind<<<1, 256>>>(mask);

    dim3 gp(D_ / 128, M_ / 128);   // (8, 32)
    gemm_mma<1><<<gp, 256, smem_bytes>>>(Q, Wq, bq, qp);
    gemm_mma<1><<<gp, 256, smem_bytes>>>(K, Wk, bk, kp);
    gemm_mma<1><<<gp, 256, smem_bytes>>>(V, Wv, bv, vp);

    scores_kernel<<<dim3(N_ / 64, N_ / 64, BH_), 256>>>(mask, wout);
    softmax_rows<<<BH_ * N_, 256>>>(wout);
    attn_kernel<<<dim3(N_ / 64, BH_), 256>>>(wout);

    gemm_mma<0><<<gp, 256, smem_bytes>>>(ap, Wo, bo, xout);
}

// round 4
// speedup vs baseline: 2.0266x; 1.2092x over previous
#include <cuda_runtime.h>
#include <cuda_bf16.h>
#include <cstdint>

// Problem constants
#define B_   4
#define N_   1024
#define D_   1024
#define H_   16
#define DH_  64
#define M_   (B_ * N_)    // 4096
#define BH_  (B_ * H_)    // 64

// Scratch (allocation-free rule: __device__ globals)
__device__ __nv_bfloat16 g_qh[(size_t)BH_ * N_ * DH_];
__device__ __nv_bfloat16 g_ql[(size_t)BH_ * N_ * DH_];
__device__ __nv_bfloat16 g_kh[(size_t)BH_ * N_ * DH_];
__device__ __nv_bfloat16 g_kl[(size_t)BH_ * N_ * DH_];
__device__ __nv_bfloat16 g_vh[(size_t)BH_ * N_ * DH_];
__device__ __nv_bfloat16 g_vl[(size_t)BH_ * N_ * DH_];
__device__ __nv_bfloat16 g_wh[(size_t)BH_ * N_ * N_];
__device__ __nv_bfloat16 g_wl[(size_t)BH_ * N_ * N_];
__device__ float g_attn[(size_t)M_ * D_];
__device__ int   g_mask4;

// ===========================================================================
// Generic-PTX tensor-core helpers
// ===========================================================================
__device__ __forceinline__ uint32_t smem_u32(const void* p) {
    uint32_t a;
    asm("{ .reg .u64 t; cvta.to.shared.u64 t, %1; cvt.u32.u64 %0, t; }" : "=r"(a) : "l"(p));
    return a;
}
__device__ __forceinline__ void ldsm_x4(uint32_t* r, uint32_t addr) {
    asm volatile("ldmatrix.sync.aligned.m8n8.x4.shared.b16 {%0,%1,%2,%3}, [%4];"
                 : "=r"(r[0]), "=r"(r[1]), "=r"(r[2]), "=r"(r[3]) : "r"(addr));
}
__device__ __forceinline__ void ldsm_x4_t(uint32_t* r, uint32_t addr) {
    asm volatile("ldmatrix.sync.aligned.m8n8.x4.trans.shared.b16 {%0,%1,%2,%3}, [%4];"
                 : "=r"(r[0]), "=r"(r[1]), "=r"(r[2]), "=r"(r[3]) : "r"(addr));
}
__device__ __forceinline__ void mma_bf16(float* c, const uint32_t* a, const uint32_t* b) {
    asm volatile(
        "mma.sync.aligned.m16n8k16.row.col.f32.bf16.bf16.f32 "
        "{%0,%1,%2,%3}, {%4,%5,%6,%7}, {%8,%9}, {%0,%1,%2,%3};"
        : "+f"(c[0]), "+f"(c[1]), "+f"(c[2]), "+f"(c[3])
        : "r"(a[0]), "r"(a[1]), "r"(a[2]), "r"(a[3]), "r"(b[0]), "r"(b[1]));
}
__device__ __forceinline__ void cvt_pair(float x0, float x1, uint32_t& hi, uint32_t& lo) {
    __nv_bfloat16 h0 = __float2bfloat16(x0);
    __nv_bfloat16 h1 = __float2bfloat16(x1);
    __nv_bfloat16 l0 = __float2bfloat16(x0 - __bfloat162float(h0));
    __nv_bfloat16 l1 = __float2bfloat16(x1 - __bfloat162float(h1));
    hi = ((uint32_t)__bfloat16_as_ushort(h1) << 16) | (uint32_t)__bfloat16_as_ushort(h0);
    lo = ((uint32_t)__bfloat16_as_ushort(l1) << 16) | (uint32_t)__bfloat16_as_ushort(l0);
}

// ===========================================================================
// bf16x3 NT GEMM: C[4096 x 1024] = A @ W^T + bias, K = 1024.  (unchanged core)
// MODE 0: fp32 row-major out. MODE 1: bf16 hi/lo head-split out [b,h,n,dh].
// ===========================================================================
#define BK_      32
#define LDS_     40
#define TILE_B   (128 * LDS_ * 2)
#define BUF_B    (4 * TILE_B)
#define NUM_KB   (D_ / BK_)

template <int MODE>
__global__ void __launch_bounds__(256, 1) gemm_mma(const float* __restrict__ A,
                                                   const float* __restrict__ W,
                                                   const float* __restrict__ bias,
                                                   float* __restrict__ C,
                                                   __nv_bfloat16* __restrict__ Chi,
                                                   __nv_bfloat16* __restrict__ Clo) {
    extern __shared__ char smem[];
    __shared__ float s_bias[128];

    const int tid = threadIdx.x;
    const int wid = tid >> 5;
    const int lane = tid & 31;
    const int warp_m = wid >> 2;
    const int warp_n = wid & 3;
    const int row0 = blockIdx.y * 128;
    const int col0 = blockIdx.x * 128;

    if (tid < 128) s_bias[tid] = bias[col0 + tid];

    const int r  = tid >> 1;
    const int ch = (tid & 1) * 16;
    const float* Ap = A + (size_t)(row0 + r) * D_ + ch;
    const float* Bp = W + (size_t)(col0 + r) * D_ + ch;
    const uint32_t st_off = (uint32_t)r * (LDS_ * 2) + (uint32_t)ch * 2;

    const uint32_t sb = smem_u32(smem);
    const int seg = lane >> 3, l7 = lane & 7;
    const int a_row = warp_m * 64 + (seg & 1) * 8 + l7;
    const int a_colb = (((seg >> 1) & 1) * 8) * 2;
    const int b_row = warp_n * 32 + ((seg >> 1) & 1) * 8 + l7;
    const int b_colb = ((seg & 1) * 8) * 2;

    float acc[4][4][4] = {};
    float fa[16], fb[16];

#pragma unroll
    for (int j = 0; j < 4; j++) {
        *(float4*)(fa + j * 4) = *(const float4*)(Ap + j * 4);
        *(float4*)(fb + j * 4) = *(const float4*)(Bp + j * 4);
    }
    {
        uint4 ah[2], al[2], bh[2], bl[2];
#pragma unroll
        for (int j = 0; j < 2; j++) {
            cvt_pair(fa[j*8+0], fa[j*8+1], ah[j].x, al[j].x);
            cvt_pair(fa[j*8+2], fa[j*8+3], ah[j].y, al[j].y);
            cvt_pair(fa[j*8+4], fa[j*8+5], ah[j].z, al[j].z);
            cvt_pair(fa[j*8+6], fa[j*8+7], ah[j].w, al[j].w);
            cvt_pair(fb[j*8+0], fb[j*8+1], bh[j].x, bl[j].x);
            cvt_pair(fb[j*8+2], fb[j*8+3], bh[j].y, bl[j].y);
            cvt_pair(fb[j*8+4], fb[j*8+5], bh[j].z, bl[j].z);
            cvt_pair(fb[j*8+6], fb[j*8+7], bh[j].w, bl[j].w);
        }
        char* base = smem;
#pragma unroll
        for (int j = 0; j < 2; j++) {
            *(uint4*)(base + 0*TILE_B + st_off + j*16) = ah[j];
            *(uint4*)(base + 1*TILE_B + st_off + j*16) = al[j];
            *(uint4*)(base + 2*TILE_B + st_off + j*16) = bh[j];
            *(uint4*)(base + 3*TILE_B + st_off + j*16) = bl[j];
        }
    }
    __syncthreads();

    for (int kb = 0; kb < NUM_KB; kb++) {
        if (kb + 1 < NUM_KB) {
            const int k0 = (kb + 1) * BK_;
#pragma unroll
            for (int j = 0; j < 4; j++) {
                *(float4*)(fa + j * 4) = *(const float4*)(Ap + k0 + j * 4);
                *(float4*)(fb + j * 4) = *(const float4*)(Bp + k0 + j * 4);
            }
        }

        const uint32_t buf = sb + (uint32_t)(kb & 1) * BUF_B;
#pragma unroll
        for (int s = 0; s < 2; s++) {
            uint32_t a_hi[4][4], a_lo[4][4], b_hi[4][2], b_lo[4][2];
#pragma unroll
            for (int mt = 0; mt < 4; mt++) {
                const uint32_t off = (uint32_t)(a_row + mt * 16) * (LDS_ * 2) + a_colb + s * 32;
                ldsm_x4(a_hi[mt], buf + 0 * TILE_B + off);
                ldsm_x4(a_lo[mt], buf + 1 * TILE_B + off);
            }
#pragma unroll
            for (int p = 0; p < 2; p++) {
                const uint32_t off = (uint32_t)(b_row + p * 16) * (LDS_ * 2) + b_colb + s * 32;
                uint32_t th[4], tl[4];
                ldsm_x4(th, buf + 2 * TILE_B + off);
                ldsm_x4(tl, buf + 3 * TILE_B + off);
                b_hi[2*p][0] = th[0]; b_hi[2*p][1] = th[1];
                b_hi[2*p+1][0] = th[2]; b_hi[2*p+1][1] = th[3];
                b_lo[2*p][0] = tl[0]; b_lo[2*p][1] = tl[1];
                b_lo[2*p+1][0] = tl[2]; b_lo[2*p+1][1] = tl[3];
            }
#pragma unroll
            for (int mt = 0; mt < 4; mt++)
#pragma unroll
                for (int nt = 0; nt < 4; nt++) {
                    mma_bf16(acc[mt][nt], a_hi[mt], b_hi[nt]);
                    mma_bf16(acc[mt][nt], a_lo[mt], b_hi[nt]);
                    mma_bf16(acc[mt][nt], a_hi[mt], b_lo[nt]);
                }
        }

        if (kb + 1 < NUM_KB) {
            uint4 ah[2], al[2], bh[2], bl[2];
#pragma unroll
            for (int j = 0; j < 2; j++) {
                cvt_pair(fa[j*8+0], fa[j*8+1], ah[j].x, al[j].x);
                cvt_pair(fa[j*8+2], fa[j*8+3], ah[j].y, al[j].y);
                cvt_pair(fa[j*8+4], fa[j*8+5], ah[j].z, al[j].z);
                cvt_pair(fa[j*8+6], fa[j*8+7], ah[j].w, al[j].w);
                cvt_pair(fb[j*8+0], fb[j*8+1], bh[j].x, bl[j].x);
                cvt_pair(fb[j*8+2], fb[j*8+3], bh[j].y, bl[j].y);
                cvt_pair(fb[j*8+4], fb[j*8+5], bh[j].z, bl[j].z);
                cvt_pair(fb[j*8+6], fb[j*8+7], bh[j].w, bl[j].w);
            }
            char* base = smem + ((kb + 1) & 1) * BUF_B;
#pragma unroll
            for (int j = 0; j < 2; j++) {
                *(uint4*)(base + 0*TILE_B + st_off + j*16) = ah[j];
                *(uint4*)(base + 1*TILE_B + st_off + j*16) = al[j];
                *(uint4*)(base + 2*TILE_B + st_off + j*16) = bh[j];
                *(uint4*)(base + 3*TILE_B + st_off + j*16) = bl[j];
            }
        }
        __syncthreads();
    }

    const int group = lane >> 2, tg = lane & 3;
#pragma unroll
    for (int mt = 0; mt < 4; mt++) {
#pragma unroll
        for (int nt = 0; nt < 4; nt++) {
#pragma unroll
            for (int rp = 0; rp < 2; rp++) {     // register pairs: cols c, c+1
                const int row = row0 + warp_m * 64 + mt * 16 + group + rp * 8;
                const int lcol = warp_n * 32 + nt * 8 + tg * 2;
                const float v0 = acc[mt][nt][rp * 2 + 0] + s_bias[lcol];
                const float v1 = acc[mt][nt][rp * 2 + 1] + s_bias[lcol + 1];
                if (MODE == 0) {
                    C[(size_t)row * D_ + col0 + lcol] = v0;
                    C[(size_t)row * D_ + col0 + lcol + 1] = v1;
                } else {
                    const int b = row >> 10;
                    const int n = row & (N_ - 1);
                    const int col = col0 + lcol;
                    const int h = col >> 6;
                    const int dh = col & (DH_ - 1);
                    const size_t idx = (((size_t)b * H_ + h) * N_ + n) * DH_ + dh;
                    __nv_bfloat16 h0 = __float2bfloat16(v0);
                    __nv_bfloat16 h1 = __float2bfloat16(v1);
                    __nv_bfloat16 l0 = __float2bfloat16(v0 - __bfloat162float(h0));
                    __nv_bfloat16 l1 = __float2bfloat16(v1 - __bfloat162float(h1));
                    *(__nv_bfloat162*)(Chi + idx) = __nv_bfloat162(h0, h1);
                    *(__nv_bfloat162*)(Clo + idx) = __nv_bfloat162(l0, l1);
                }
            }
        }
    }
}

// ===========================================================================
// Mask dtype detection (unchanged)
// ===========================================================================
__global__ void detect_mask_kind(const unsigned char* __restrict__ m) {
    __shared__ int has_gt1, has_mis;
    if (threadIdx.x == 0) { has_gt1 = 0; has_mis = 0; }
    __syncthreads();
    int lg = 0, lm = 0;
    for (int i = threadIdx.x * 16; i < 65536; i += blockDim.x * 16) {
        uint4 v = *(const uint4*)(m + i);
        unsigned int w[4] = {v.x, v.y, v.z, v.w};
#pragma unroll
        for (int j = 0; j < 4; j++) {
#pragma unroll
            for (int b = 0; b < 4; b++) {
                unsigned int byte = (w[j] >> (8 * b)) & 0xFFu;
                int pos = i + j * 4 + b;
                if (byte > 1u) lg = 1;
                if (byte != 0u && (pos & 3)) lm = 1;
            }
        }
    }
    if (lg) atomicOr(&has_gt1, 1);
    if (lm) atomicOr(&has_mis, 1);
    __syncthreads();
    if (threadIdx.x == 0) g_mask4 = (has_gt1 || !has_mis) ? 1 : 0;
}

// ===========================================================================
// Scores via mma, bf16x3: S = q @ k^T / 8, masked.  128x128 tile, K=64.
// ===========================================================================
#define LDQ  72                       // bf16 elems per padded smem row
#define QT_B (128 * LDQ * 2)          // 18432 bytes per tile

__global__ void __launch_bounds__(256, 1) scores_mma(const unsigned char* __restrict__ maskp,
                                                     float* __restrict__ wout) {
    extern __shared__ char smem[];
    const int tid = threadIdx.x;
    const int wid = tid >> 5;
    const int lane = tid & 31;
    const int warp_m = wid >> 2;
    const int warp_n = wid & 3;
    const int bh = blockIdx.z;
    const int row0 = blockIdx.y * 128;
    const int col0 = blockIdx.x * 128;

    // load q,k tiles (hi/lo) into smem
    const int r = tid >> 1;
    const int half = tid & 1;
    const size_t qsrc = (size_t)bh * N_ * DH_ + (size_t)(row0 + r) * DH_ + half * 32;
    const size_t ksrc = (size_t)bh * N_ * DH_ + (size_t)(col0 + r) * DH_ + half * 32;
    const uint32_t dst = (uint32_t)r * (LDQ * 2) + (uint32_t)half * 64;
#pragma unroll
    for (int j = 0; j < 4; j++) {
        *(uint4*)(smem + 0*QT_B + dst + j*16) = *(const uint4*)(g_qh + qsrc + j*8);
        *(uint4*)(smem + 1*QT_B + dst + j*16) = *(const uint4*)(g_ql + qsrc + j*8);
        *(uint4*)(smem + 2*QT_B + dst + j*16) = *(const uint4*)(g_kh + ksrc + j*8);
        *(uint4*)(smem + 3*QT_B + dst + j*16) = *(const uint4*)(g_kl + ksrc + j*8);
    }
    __syncthreads();

    const uint32_t sb = smem_u32(smem);
    const int seg = lane >> 3, l7 = lane & 7;
    const int a_row = warp_m * 64 + (seg & 1) * 8 + l7;
    const int a_colb = (((seg >> 1) & 1) * 8) * 2;
    const int b_row = warp_n * 32 + ((seg >> 1) & 1) * 8 + l7;
    const int b_colb = ((seg & 1) * 8) * 2;

    float acc[4][4][4] = {};
#pragma unroll
    for (int s = 0; s < 4; s++) {
        uint32_t a_hi[4][4], a_lo[4][4], b_hi[4][2], b_lo[4][2];
#pragma unroll
        for (int mt = 0; mt < 4; mt++) {
            const uint32_t off = (uint32_t)(a_row + mt * 16) * (LDQ * 2) + a_colb + s * 32;
            ldsm_x4(a_hi[mt], sb + 0 * QT_B + off);
            ldsm_x4(a_lo[mt], sb + 1 * QT_B + off);
        }
#pragma unroll
        for (int p = 0; p < 2; p++) {
            const uint32_t off = (uint32_t)(b_row + p * 16) * (LDQ * 2) + b_colb + s * 32;
            uint32_t th[4], tl[4];
            ldsm_x4(th, sb + 2 * QT_B + off);
            ldsm_x4(tl, sb + 3 * QT_B + off);
            b_hi[2*p][0] = th[0]; b_hi[2*p][1] = th[1];
            b_hi[2*p+1][0] = th[2]; b_hi[2*p+1][1] = th[3];
            b_lo[2*p][0] = tl[0]; b_lo[2*p][1] = tl[1];
            b_lo[2*p+1][0] = tl[2]; b_lo[2*p+1][1] = tl[3];
        }
#pragma unroll
        for (int mt = 0; mt < 4; mt++)
#pragma unroll
            for (int nt = 0; nt < 4; nt++) {
                mma_bf16(acc[mt][nt], a_hi[mt], b_hi[nt]);
                mma_bf16(acc[mt][nt], a_lo[mt], b_hi[nt]);
                mma_bf16(acc[mt][nt], a_hi[mt], b_lo[nt]);
            }
    }

    const int group = lane >> 2, tg = lane & 3;
    const int m4 = g_mask4;
    const unsigned int* mask32 = (const unsigned int*)maskp;
#pragma unroll
    for (int mt = 0; mt < 4; mt++)
#pragma unroll
        for (int nt = 0; nt < 4; nt++)
#pragma unroll
            for (int rg = 0; rg < 4; rg++) {
                const int row = row0 + warp_m * 64 + mt * 16 + group + (rg >> 1) * 8;
                const int col = col0 + warp_n * 32 + nt * 8 + tg * 2 + (rg & 1);
                const size_t idx = ((size_t)bh * N_ + row) * N_ + col;
                const bool masked = m4 ? (mask32[idx] != 0u) : (maskp[idx] != 0);
                wout[idx] = masked ? -1e10f : acc[mt][nt][rg] * 0.125f;
            }
}

// ===========================================================================
// Row softmax; writes fp32 weights + bf16 hi/lo copies for attn GEMM.
// ===========================================================================
__global__ void __launch_bounds__(256) softmax_rows(float* __restrict__ w) {
    const size_t base = (size_t)blockIdx.x * N_;
    float* p = w + base;
    float4 v = ((float4*)p)[threadIdx.x];

    __shared__ float smax[8];
    __shared__ float ssum[8];
    const int warp = threadIdx.x >> 5, lane = threadIdx.x & 31;

    float m = fmaxf(fmaxf(v.x, v.y), fmaxf(v.z, v.w));
#pragma unroll
    for (int o = 16; o; o >>= 1) m = fmaxf(m, __shfl_xor_sync(~0u, m, o));
    if (lane == 0) smax[warp] = m;
    __syncthreads();
    if (warp == 0) {
        float t = (lane < 8) ? smax[lane] : -3.4e38f;
#pragma unroll
        for (int o = 4; o; o >>= 1) t = fmaxf(t, __shfl_xor_sync(~0u, t, o));
        if (lane == 0) smax[0] = t;
    }
    __syncthreads();
    m = smax[0];

    v.x = __expf(v.x - m); v.y = __expf(v.y - m);
    v.z = __expf(v.z - m); v.w = __expf(v.w - m);
    float s = v.x + v.y + v.z + v.w;
#pragma unroll
    for (int o = 16; o; o >>= 1) s += __shfl_xor_sync(~0u, s, o);
    if (lane == 0) ssum[warp] = s;
    __syncthreads();
    if (warp == 0) {
        float t = (lane < 8) ? ssum[lane] : 0.0f;
#pragma unroll
        for (int o = 4; o; o >>= 1) t += __shfl_xor_sync(~0u, t, o);
        if (lane == 0) ssum[0] = t;
    }
    __syncthreads();
    const float inv = 1.0f / ssum[0];
    v.x *= inv; v.y *= inv; v.z *= inv; v.w *= inv;
    ((float4*)p)[threadIdx.x] = v;

    // bf16 hi/lo copies
    __nv_bfloat16 h0 = __float2bfloat16(v.x), h1 = __float2bfloat16(v.y);
    __nv_bfloat16 h2 = __float2bfloat16(v.z), h3 = __float2bfloat16(v.w);
    __nv_bfloat16 l0 = __float2bfloat16(v.x - __bfloat162float(h0));
    __nv_bfloat16 l1 = __float2bfloat16(v.y - __bfloat162float(h1));
    __nv_bfloat16 l2 = __float2bfloat16(v.z - __bfloat162float(h2));
    __nv_bfloat16 l3 = __float2bfloat16(v.w - __bfloat162float(h3));
    const size_t off = base + threadIdx.x * 4;
    *(__nv_bfloat162*)(g_wh + off)     = __nv_bfloat162(h0, h1);
    *(__nv_bfloat162*)(g_wh + off + 2) = __nv_bfloat162(h2, h3);
    *(__nv_bfloat162*)(g_wl + off)     = __nv_bfloat162(l0, l1);
    *(__nv_bfloat162*)(g_wl + off + 2) = __nv_bfloat162(l2, l3);
}

// ===========================================================================
// attn = weights @ v via mma, bf16x3.  Tile: 128 rows x 64 dh, K=1024, BK=64.
// A = weights hi/lo [m][k] row-major, B = v hi/lo [k][dh] via ldmatrix.trans.
// ===========================================================================
#define AT_B   (128 * LDQ * 2)        // 18432: weights tile (128 x 64 bf16, pad 72)
#define VT_B   (64 * LDQ * 2)         // 9216:  v tile (64 x 64 bf16, pad 72)
#define AB_B   (2 * AT_B + 2 * VT_B)  // 55296 per buffer
#define NKB_A  (N_ / 64)              // 16

__global__ void __launch_bounds__(256, 1) attn_mma(void) {
    extern __shared__ char smem[];
    const int tid = threadIdx.x;
    const int wid = tid >> 5;
    const int lane = tid & 31;
    const int warp_m = wid >> 1;      // 0..3 -> 32 rows each
    const int warp_n = wid & 1;       // 0..1 -> 32 dh each
    const int bh = blockIdx.y;
    const int row0 = blockIdx.x * 128;

    const __nv_bfloat16* whb = g_wh + (size_t)bh * N_ * N_;
    const __nv_bfloat16* wlb = g_wl + (size_t)bh * N_ * N_;
    const __nv_bfloat16* vhb = g_vh + (size_t)bh * N_ * DH_;
    const __nv_bfloat16* vlb = g_vl + (size_t)bh * N_ * DH_;

    // load mappings
    const int ar = tid >> 1, ahalf = tid & 1;              // weights: 128 rows, 2 thr/row
    const uint32_t a_dst = (uint32_t)ar * (LDQ * 2) + (uint32_t)ahalf * 64;
    const int vr = tid >> 2, vq = tid & 3;                 // v: 64 rows, 4 thr/row
    const uint32_t v_dst = (uint32_t)vr * (LDQ * 2) + (uint32_t)vq * 32;

    // prologue: load k-block 0 into buffer 0
    {
        const size_t asrc = (size_t)(row0 + ar) * N_ + ahalf * 32;
        const size_t vsrc = (size_t)vr * DH_ + vq * 16;
#pragma unroll
        for (int j = 0; j < 4; j++) {
            *(uint4*)(smem + 0*AT_B + a_dst + j*16) = *(const uint4*)(whb + asrc + j*8);
            *(uint4*)(smem + 1*AT_B + a_dst + j*16) = *(const uint4*)(wlb + asrc + j*8);
        }
#pragma unroll
        for (int j = 0; j < 2; j++) {
            *(uint4*)(smem + 2*AT_B + 0*VT_B + v_dst + j*16) = *(const uint4*)(vhb + vsrc + j*8);
            *(uint4*)(smem + 2*AT_B + 1*VT_B + v_dst + j*16) = *(const uint4*)(vlb + vsrc + j*8);
        }
    }
    __syncthreads();

    const uint32_t sb = smem_u32(smem);
    const int l15 = lane & 15;
    const int a_row = warp_m * 32 + l15;
    const int a_colb = (lane >> 4) * 16;
    const int v_row = l15;
    const int v_colb = (warp_n * 32) * 2 + (lane >> 4) * 16;

    float acc[2][4][4] = {};
    uint4 pa[8], pv[4];

    for (int kb = 0; kb < NKB_A; kb++) {
        // prefetch next block
        if (kb + 1 < NKB_A) {
            const int k0 = (kb + 1) * 64;
            const size_t asrc = (size_t)(row0 + ar) * N_ + k0 + ahalf * 32;
            const size_t vsrc = (size_t)(k0 + vr) * DH_ + vq * 16;
#pragma unroll
            for (int j = 0; j < 4; j++) {
                pa[j]     = *(const uint4*)(whb + asrc + j*8);
                pa[4 + j] = *(const uint4*)(wlb + asrc + j*8);
            }
#pragma unroll
            for (int j = 0; j < 2; j++) {
                pv[j]     = *(const uint4*)(vhb + vsrc + j*8);
                pv[2 + j] = *(const uint4*)(vlb + vsrc + j*8);
            }
        }

        const uint32_t buf = sb + (uint32_t)(kb & 1) * AB_B;
#pragma unroll
        for (int s = 0; s < 4; s++) {
            uint32_t a_hi[2][4], a_lo[2][4], b_hi[4][2], b_lo[4][2];
#pragma unroll
            for (int mt = 0; mt < 2; mt++) {
                const uint32_t off = (uint32_t)(a_row + mt * 16) * (LDQ * 2) + a_colb + s * 32;
                ldsm_x4(a_hi[mt], buf + 0 * AT_B + off);
                ldsm_x4(a_lo[mt], buf + 1 * AT_B + off);
            }
#pragma unroll
            for (int p = 0; p < 2; p++) {
                const uint32_t off = (uint32_t)(s * 16 + v_row) * (LDQ * 2) + v_colb + p * 32;
                uint32_t th[4], tl[4];
                ldsm_x4_t(th, buf + 2 * AT_B + 0 * VT_B + off);
                ldsm_x4_t(tl, buf + 2 * AT_B + 1 * VT_B + off);
                b_hi[2*p][0] = th[0]; b_hi[2*p][1] = th[1];
                b_hi[2*p+1][0] = th[2]; b_hi[2*p+1][1] = th[3];
                b_lo[2*p][0] = tl[0]; b_lo[2*p][1] = tl[1];
                b_lo[2*p+1][0] = tl[2]; b_lo[2*p+1][1] = tl[3];
            }
#pragma unroll
            for (int mt = 0; mt < 2; mt++)
#pragma unroll
                for (int nt = 0; nt < 4; nt++) {
                    mma_bf16(acc[mt][nt], a_hi[mt], b_hi[nt]);
                    mma_bf16(acc[mt][nt], a_lo[mt], b_hi[nt]);
                    mma_bf16(acc[mt][nt], a_hi[mt], b_lo[nt]);
                }
        }

        if (kb + 1 < NKB_A) {
            char* base = smem + ((kb + 1) & 1) * AB_B;
#pragma unroll
            for (int j = 0; j < 4; j++) {
                *(uint4*)(base + 0*AT_B + a_dst + j*16) = pa[j];
                *(uint4*)(base + 1*AT_B + a_dst + j*16) = pa[4 + j];
            }
#pragma unroll
            for (int j = 0; j < 2; j++) {
                *(uint4*)(base + 2*AT_B + 0*VT_B + v_dst + j*16) = pv[j];
                *(uint4*)(base + 2*AT_B + 1*VT_B + v_dst + j*16) = pv[2 + j];
            }
        }
        __syncthreads();
    }

    // epilogue: write g_attn [b, n, h*64 + dh]
    const int b = bh >> 4;
    const int h = bh & (H_ - 1);
    const int group = lane >> 2, tg = lane & 3;
#pragma unroll
    for (int mt = 0; mt < 2; mt++)
#pragma unroll
        for (int nt = 0; nt < 4; nt++)
#pragma unroll
            for (int rp = 0; rp < 2; rp++) {
                const int n = row0 + warp_m * 32 + mt * 16 + group + rp * 8;
                const int dh = warp_n * 32 + nt * 8 + tg * 2;
                float* dst = &g_attn[((size_t)b * N_ + n) * D_ + h * DH_ + dh];
                dst[0] = acc[mt][nt][rp * 2 + 0];
                dst[1] = acc[mt][nt][rp * 2 + 1];
            }
}

// ===========================================================================
extern "C" void kernel_launch(void* const* d_in, const int* in_sizes, int n_in,
                              void* d_out, int out_size) {
    const float* Q  = (const float*)d_in[0];
    const float* K  = (const float*)d_in[1];
    const float* V  = (const float*)d_in[2];
    const unsigned char* mask = (const unsigned char*)d_in[3];
    const float* Wq = (const float*)d_in[4];
    const float* bq = (const float*)d_in[5];
    const float* Wk = (const float*)d_in[6];
    const float* bk = (const float*)d_in[7];
    const float* Wv = (const float*)d_in[8];
    const float* bv = (const float*)d_in[9];
    const float* Wo = (const float*)d_in[10];
    const float* bo = (const float*)d_in[11];

    float* xout = (float*)d_out;
    float* wout = xout + (size_t)M_ * D_;

    __nv_bfloat16 *qh, *ql, *kh, *kl, *vh, *vl;
    float* ap;
    cudaGetSymbolAddress((void**)&qh, g_qh);
    cudaGetSymbolAddress((void**)&ql, g_ql);
    cudaGetSymbolAddress((void**)&kh, g_kh);
    cudaGetSymbolAddress((void**)&kl, g_kl);
    cudaGetSymbolAddress((void**)&vh, g_vh);
    cudaGetSymbolAddress((void**)&vl, g_vl);
    cudaGetSymbolAddress((void**)&ap, g_attn);

    const int gemm_smem = 2 * BUF_B;            // 81920
    const int scores_smem = 4 * QT_B;           // 73728
    const int attn_smem = 2 * AB_B;             // 110592
    cudaFuncSetAttribute(gemm_mma<0>, cudaFuncAttributeMaxDynamicSharedMemorySize, gemm_smem);
    cudaFuncSetAttribute(gemm_mma<1>, cudaFuncAttributeMaxDynamicSharedMemorySize, gemm_smem);
    cudaFuncSetAttribute(scores_mma, cudaFuncAttributeMaxDynamicSharedMemorySize, scores_smem);
    cudaFuncSetAttribute(attn_mma, cudaFuncAttributeMaxDynamicSharedMemorySize, attn_smem);

    detect_mask_kind<<<1, 256>>>(mask);

    dim3 gp(D_ / 128, M_ / 128);   // (8, 32)
    gemm_mma<1><<<gp, 256, gemm_smem>>>(Q, Wq, bq, nullptr, qh, ql);
    gemm_mma<1><<<gp, 256, gemm_smem>>>(K, Wk, bk, nullptr, kh, kl);
    gemm_mma<1><<<gp, 256, gemm_smem>>>(V, Wv, bv, nullptr, vh, vl);

    scores_mma<<<dim3(N_ / 128, N_ / 128, BH_), 256, scores_smem>>>(mask, wout);
    softmax_rows<<<BH_ * N_, 256>>>(wout);
    attn_mma<<<dim3(N_ / 128, BH_), 256, attn_smem>>>();

    gemm_mma<0><<<gp, 256, gemm_smem>>>(ap, Wo, bo, xout, nullptr, nullptr);
}

// round 5
// speedup vs baseline: 2.0416x; 1.0074x over previous
#include <cuda_runtime.h>
#include <cuda_bf16.h>
#include <cstdint>

// Problem constants
#define B_   4
#define N_   1024
#define D_   1024
#define H_   16
#define DH_  64
#define M_   (B_ * N_)    // 4096
#define BH_  (B_ * H_)    // 64

// Scratch (allocation-free rule: __device__ globals)
__device__ __nv_bfloat16 g_qh[(size_t)BH_ * N_ * DH_];
__device__ __nv_bfloat16 g_ql[(size_t)BH_ * N_ * DH_];
__device__ __nv_bfloat16 g_kh[(size_t)BH_ * N_ * DH_];
__device__ __nv_bfloat16 g_kl[(size_t)BH_ * N_ * DH_];
__device__ __nv_bfloat16 g_vh[(size_t)BH_ * N_ * DH_];
__device__ __nv_bfloat16 g_vl[(size_t)BH_ * N_ * DH_];
__device__ __nv_bfloat16 g_wh[(size_t)BH_ * N_ * N_];
__device__ __nv_bfloat16 g_wl[(size_t)BH_ * N_ * N_];
__device__ float g_attn[(size_t)M_ * D_];
__device__ int   g_mask4;

// ===========================================================================
// Generic-PTX tensor-core helpers
// ===========================================================================
__device__ __forceinline__ uint32_t smem_u32(const void* p) {
    uint32_t a;
    asm("{ .reg .u64 t; cvta.to.shared.u64 t, %1; cvt.u32.u64 %0, t; }" : "=r"(a) : "l"(p));
    return a;
}
__device__ __forceinline__ void ldsm_x4(uint32_t* r, uint32_t addr) {
    asm volatile("ldmatrix.sync.aligned.m8n8.x4.shared.b16 {%0,%1,%2,%3}, [%4];"
                 : "=r"(r[0]), "=r"(r[1]), "=r"(r[2]), "=r"(r[3]) : "r"(addr));
}
__device__ __forceinline__ void ldsm_x4_t(uint32_t* r, uint32_t addr) {
    asm volatile("ldmatrix.sync.aligned.m8n8.x4.trans.shared.b16 {%0,%1,%2,%3}, [%4];"
                 : "=r"(r[0]), "=r"(r[1]), "=r"(r[2]), "=r"(r[3]) : "r"(addr));
}
__device__ __forceinline__ void mma_bf16(float* c, const uint32_t* a, const uint32_t* b) {
    asm volatile(
        "mma.sync.aligned.m16n8k16.row.col.f32.bf16.bf16.f32 "
        "{%0,%1,%2,%3}, {%4,%5,%6,%7}, {%8,%9}, {%0,%1,%2,%3};"
        : "+f"(c[0]), "+f"(c[1]), "+f"(c[2]), "+f"(c[3])
        : "r"(a[0]), "r"(a[1]), "r"(a[2]), "r"(a[3]), "r"(b[0]), "r"(b[1]));
}
__device__ __forceinline__ void cvt_pair(float x0, float x1, uint32_t& hi, uint32_t& lo) {
    __nv_bfloat16 h0 = __float2bfloat16(x0);
    __nv_bfloat16 h1 = __float2bfloat16(x1);
    __nv_bfloat16 l0 = __float2bfloat16(x0 - __bfloat162float(h0));
    __nv_bfloat16 l1 = __float2bfloat16(x1 - __bfloat162float(h1));
    hi = ((uint32_t)__bfloat16_as_ushort(h1) << 16) | (uint32_t)__bfloat16_as_ushort(h0);
    lo = ((uint32_t)__bfloat16_as_ushort(l1) << 16) | (uint32_t)__bfloat16_as_ushort(l0);
}

// ===========================================================================
// bf16x3 NT GEMM: C[4096 x 1024] = A @ W^T + bias, K = 1024.
// Inner MMAs issued in 3 independent passes (hi*hi, lo*hi, hi*lo) so that
// same-accumulator MMAs are 16 issue slots apart -> pipelined, not chained.
// MODE 0: fp32 row-major out. MODE 1: bf16 hi/lo head-split out [b,h,n,dh].
// ===========================================================================
#define BK_      32
#define LDS_     40
#define TILE_B   (128 * LDS_ * 2)
#define BUF_B    (4 * TILE_B)
#define NUM_KB   (D_ / BK_)

template <int MODE>
__global__ void __launch_bounds__(256, 1) gemm_mma(const float* __restrict__ A,
                                                   const float* __restrict__ W,
                                                   const float* __restrict__ bias,
                                                   float* __restrict__ C,
                                                   __nv_bfloat16* __restrict__ Chi,
                                                   __nv_bfloat16* __restrict__ Clo) {
    extern __shared__ char smem[];
    __shared__ float s_bias[128];

    const int tid = threadIdx.x;
    const int wid = tid >> 5;
    const int lane = tid & 31;
    const int warp_m = wid >> 2;
    const int warp_n = wid & 3;
    const int row0 = blockIdx.y * 128;
    const int col0 = blockIdx.x * 128;

    if (tid < 128) s_bias[tid] = bias[col0 + tid];

    const int r  = tid >> 1;
    const int ch = (tid & 1) * 16;
    const float* Ap = A + (size_t)(row0 + r) * D_ + ch;
    const float* Bp = W + (size_t)(col0 + r) * D_ + ch;
    const uint32_t st_off = (uint32_t)r * (LDS_ * 2) + (uint32_t)ch * 2;

    const uint32_t sb = smem_u32(smem);
    const int seg = lane >> 3, l7 = lane & 7;
    const int a_row = warp_m * 64 + (seg & 1) * 8 + l7;
    const int a_colb = (((seg >> 1) & 1) * 8) * 2;
    const int b_row = warp_n * 32 + ((seg >> 1) & 1) * 8 + l7;
    const int b_colb = ((seg & 1) * 8) * 2;

    float acc[4][4][4] = {};
    float fa[16], fb[16];

#pragma unroll
    for (int j = 0; j < 4; j++) {
        *(float4*)(fa + j * 4) = *(const float4*)(Ap + j * 4);
        *(float4*)(fb + j * 4) = *(const float4*)(Bp + j * 4);
    }
    {
        uint4 ah[2], al[2], bh[2], bl[2];
#pragma unroll
        for (int j = 0; j < 2; j++) {
            cvt_pair(fa[j*8+0], fa[j*8+1], ah[j].x, al[j].x);
            cvt_pair(fa[j*8+2], fa[j*8+3], ah[j].y, al[j].y);
            cvt_pair(fa[j*8+4], fa[j*8+5], ah[j].z, al[j].z);
            cvt_pair(fa[j*8+6], fa[j*8+7], ah[j].w, al[j].w);
            cvt_pair(fb[j*8+0], fb[j*8+1], bh[j].x, bl[j].x);
            cvt_pair(fb[j*8+2], fb[j*8+3], bh[j].y, bl[j].y);
            cvt_pair(fb[j*8+4], fb[j*8+5], bh[j].z, bl[j].z);
            cvt_pair(fb[j*8+6], fb[j*8+7], bh[j].w, bl[j].w);
        }
        char* base = smem;
#pragma unroll
        for (int j = 0; j < 2; j++) {
            *(uint4*)(base + 0*TILE_B + st_off + j*16) = ah[j];
            *(uint4*)(base + 1*TILE_B + st_off + j*16) = al[j];
            *(uint4*)(base + 2*TILE_B + st_off + j*16) = bh[j];
            *(uint4*)(base + 3*TILE_B + st_off + j*16) = bl[j];
        }
    }
    __syncthreads();

    for (int kb = 0; kb < NUM_KB; kb++) {
        if (kb + 1 < NUM_KB) {
            const int k0 = (kb + 1) * BK_;
#pragma unroll
            for (int j = 0; j < 4; j++) {
                *(float4*)(fa + j * 4) = *(const float4*)(Ap + k0 + j * 4);
                *(float4*)(fb + j * 4) = *(const float4*)(Bp + k0 + j * 4);
            }
        }

        const uint32_t buf = sb + (uint32_t)(kb & 1) * BUF_B;
#pragma unroll
        for (int s = 0; s < 2; s++) {
            uint32_t a_hi[4][4], a_lo[4][4], b_hi[4][2], b_lo[4][2];
#pragma unroll
            for (int mt = 0; mt < 4; mt++) {
                const uint32_t off = (uint32_t)(a_row + mt * 16) * (LDS_ * 2) + a_colb + s * 32;
                ldsm_x4(a_hi[mt], buf + 0 * TILE_B + off);
                ldsm_x4(a_lo[mt], buf + 1 * TILE_B + off);
            }
#pragma unroll
            for (int p = 0; p < 2; p++) {
                const uint32_t off = (uint32_t)(b_row + p * 16) * (LDS_ * 2) + b_colb + s * 32;
                uint32_t th[4], tl[4];
                ldsm_x4(th, buf + 2 * TILE_B + off);
                ldsm_x4(tl, buf + 3 * TILE_B + off);
                b_hi[2*p][0] = th[0]; b_hi[2*p][1] = th[1];
                b_hi[2*p+1][0] = th[2]; b_hi[2*p+1][1] = th[3];
                b_lo[2*p][0] = tl[0]; b_lo[2*p][1] = tl[1];
                b_lo[2*p+1][0] = tl[2]; b_lo[2*p+1][1] = tl[3];
            }
            // pass 1: hi*hi  (16 independent accumulators)
#pragma unroll
            for (int mt = 0; mt < 4; mt++)
#pragma unroll
                for (int nt = 0; nt < 4; nt++)
                    mma_bf16(acc[mt][nt], a_hi[mt], b_hi[nt]);
            // pass 2: lo*hi
#pragma unroll
            for (int mt = 0; mt < 4; mt++)
#pragma unroll
                for (int nt = 0; nt < 4; nt++)
                    mma_bf16(acc[mt][nt], a_lo[mt], b_hi[nt]);
            // pass 3: hi*lo
#pragma unroll
            for (int mt = 0; mt < 4; mt++)
#pragma unroll
                for (int nt = 0; nt < 4; nt++)
                    mma_bf16(acc[mt][nt], a_hi[mt], b_lo[nt]);
        }

        if (kb + 1 < NUM_KB) {
            uint4 ah[2], al[2], bh[2], bl[2];
#pragma unroll
            for (int j = 0; j < 2; j++) {
                cvt_pair(fa[j*8+0], fa[j*8+1], ah[j].x, al[j].x);
                cvt_pair(fa[j*8+2], fa[j*8+3], ah[j].y, al[j].y);
                cvt_pair(fa[j*8+4], fa[j*8+5], ah[j].z, al[j].z);
                cvt_pair(fa[j*8+6], fa[j*8+7], ah[j].w, al[j].w);
                cvt_pair(fb[j*8+0], fb[j*8+1], bh[j].x, bl[j].x);
                cvt_pair(fb[j*8+2], fb[j*8+3], bh[j].y, bl[j].y);
                cvt_pair(fb[j*8+4], fb[j*8+5], bh[j].z, bl[j].z);
                cvt_pair(fb[j*8+6], fb[j*8+7], bh[j].w, bl[j].w);
            }
            char* base = smem + ((kb + 1) & 1) * BUF_B;
#pragma unroll
            for (int j = 0; j < 2; j++) {
                *(uint4*)(base + 0*TILE_B + st_off + j*16) = ah[j];
                *(uint4*)(base + 1*TILE_B + st_off + j*16) = al[j];
                *(uint4*)(base + 2*TILE_B + st_off + j*16) = bh[j];
                *(uint4*)(base + 3*TILE_B + st_off + j*16) = bl[j];
            }
        }
        __syncthreads();
    }

    const int group = lane >> 2, tg = lane & 3;
#pragma unroll
    for (int mt = 0; mt < 4; mt++) {
#pragma unroll
        for (int nt = 0; nt < 4; nt++) {
#pragma unroll
            for (int rp = 0; rp < 2; rp++) {
                const int row = row0 + warp_m * 64 + mt * 16 + group + rp * 8;
                const int lcol = warp_n * 32 + nt * 8 + tg * 2;
                const float v0 = acc[mt][nt][rp * 2 + 0] + s_bias[lcol];
                const float v1 = acc[mt][nt][rp * 2 + 1] + s_bias[lcol + 1];
                if (MODE == 0) {
                    C[(size_t)row * D_ + col0 + lcol] = v0;
                    C[(size_t)row * D_ + col0 + lcol + 1] = v1;
                } else {
                    const int b = row >> 10;
                    const int n = row & (N_ - 1);
                    const int col = col0 + lcol;
                    const int h = col >> 6;
                    const int dh = col & (DH_ - 1);
                    const size_t idx = (((size_t)b * H_ + h) * N_ + n) * DH_ + dh;
                    __nv_bfloat16 h0 = __float2bfloat16(v0);
                    __nv_bfloat16 h1 = __float2bfloat16(v1);
                    __nv_bfloat16 l0 = __float2bfloat16(v0 - __bfloat162float(h0));
                    __nv_bfloat16 l1 = __float2bfloat16(v1 - __bfloat162float(h1));
                    *(__nv_bfloat162*)(Chi + idx) = __nv_bfloat162(h0, h1);
                    *(__nv_bfloat162*)(Clo + idx) = __nv_bfloat162(l0, l1);
                }
            }
        }
    }
}

// ===========================================================================
// Mask dtype detection (unchanged)
// ===========================================================================
__global__ void detect_mask_kind(const unsigned char* __restrict__ m) {
    __shared__ int has_gt1, has_mis;
    if (threadIdx.x == 0) { has_gt1 = 0; has_mis = 0; }
    __syncthreads();
    int lg = 0, lm = 0;
    for (int i = threadIdx.x * 16; i < 65536; i += blockDim.x * 16) {
        uint4 v = *(const uint4*)(m + i);
        unsigned int w[4] = {v.x, v.y, v.z, v.w};
#pragma unroll
        for (int j = 0; j < 4; j++) {
#pragma unroll
            for (int b = 0; b < 4; b++) {
                unsigned int byte = (w[j] >> (8 * b)) & 0xFFu;
                int pos = i + j * 4 + b;
                if (byte > 1u) lg = 1;
                if (byte != 0u && (pos & 3)) lm = 1;
            }
        }
    }
    if (lg) atomicOr(&has_gt1, 1);
    if (lm) atomicOr(&has_mis, 1);
    __syncthreads();
    if (threadIdx.x == 0) g_mask4 = (has_gt1 || !has_mis) ? 1 : 0;
}

// ===========================================================================
// Scores via mma, bf16x3 (3-pass issue order): S = q @ k^T / 8, masked.
// ===========================================================================
#define LDQ  72
#define QT_B (128 * LDQ * 2)

__global__ void __launch_bounds__(256, 1) scores_mma(const unsigned char* __restrict__ maskp,
                                                     float* __restrict__ wout) {
    extern __shared__ char smem[];
    const int tid = threadIdx.x;
    const int wid = tid >> 5;
    const int lane = tid & 31;
    const int warp_m = wid >> 2;
    const int warp_n = wid & 3;
    const int bh = blockIdx.z;
    const int row0 = blockIdx.y * 128;
    const int col0 = blockIdx.x * 128;

    const int r = tid >> 1;
    const int half = tid & 1;
    const size_t qsrc = (size_t)bh * N_ * DH_ + (size_t)(row0 + r) * DH_ + half * 32;
    const size_t ksrc = (size_t)bh * N_ * DH_ + (size_t)(col0 + r) * DH_ + half * 32;
    const uint32_t dst = (uint32_t)r * (LDQ * 2) + (uint32_t)half * 64;
#pragma unroll
    for (int j = 0; j < 4; j++) {
        *(uint4*)(smem + 0*QT_B + dst + j*16) = *(const uint4*)(g_qh + qsrc + j*8);
        *(uint4*)(smem + 1*QT_B + dst + j*16) = *(const uint4*)(g_ql + qsrc + j*8);
        *(uint4*)(smem + 2*QT_B + dst + j*16) = *(const uint4*)(g_kh + ksrc + j*8);
        *(uint4*)(smem + 3*QT_B + dst + j*16) = *(const uint4*)(g_kl + ksrc + j*8);
    }
    __syncthreads();

    const uint32_t sb = smem_u32(smem);
    const int seg = lane >> 3, l7 = lane & 7;
    const int a_row = warp_m * 64 + (seg & 1) * 8 + l7;
    const int a_colb = (((seg >> 1) & 1) * 8) * 2;
    const int b_row = warp_n * 32 + ((seg >> 1) & 1) * 8 + l7;
    const int b_colb = ((seg & 1) * 8) * 2;

    float acc[4][4][4] = {};
#pragma unroll
    for (int s = 0; s < 4; s++) {
        uint32_t a_hi[4][4], a_lo[4][4], b_hi[4][2], b_lo[4][2];
#pragma unroll
        for (int mt = 0; mt < 4; mt++) {
            const uint32_t off = (uint32_t)(a_row + mt * 16) * (LDQ * 2) + a_colb + s * 32;
            ldsm_x4(a_hi[mt], sb + 0 * QT_B + off);
            ldsm_x4(a_lo[mt], sb + 1 * QT_B + off);
        }
#pragma unroll
        for (int p = 0; p < 2; p++) {
            const uint32_t off = (uint32_t)(b_row + p * 16) * (LDQ * 2) + b_colb + s * 32;
            uint32_t th[4], tl[4];
            ldsm_x4(th, sb + 2 * QT_B + off);
            ldsm_x4(tl, sb + 3 * QT_B + off);
            b_hi[2*p][0] = th[0]; b_hi[2*p][1] = th[1];
            b_hi[2*p+1][0] = th[2]; b_hi[2*p+1][1] = th[3];
            b_lo[2*p][0] = tl[0]; b_lo[2*p][1] = tl[1];
            b_lo[2*p+1][0] = tl[2]; b_lo[2*p+1][1] = tl[3];
        }
#pragma unroll
        for (int mt = 0; mt < 4; mt++)
#pragma unroll
            for (int nt = 0; nt < 4; nt++)
                mma_bf16(acc[mt][nt], a_hi[mt], b_hi[nt]);
#pragma unroll
        for (int mt = 0; mt < 4; mt++)
#pragma unroll
            for (int nt = 0; nt < 4; nt++)
                mma_bf16(acc[mt][nt], a_lo[mt], b_hi[nt]);
#pragma unroll
        for (int mt = 0; mt < 4; mt++)
#pragma unroll
            for (int nt = 0; nt < 4; nt++)
                mma_bf16(acc[mt][nt], a_hi[mt], b_lo[nt]);
    }

    const int group = lane >> 2, tg = lane & 3;
    const int m4 = g_mask4;
    const unsigned int* mask32 = (const unsigned int*)maskp;
#pragma unroll
    for (int mt = 0; mt < 4; mt++)
#pragma unroll
        for (int nt = 0; nt < 4; nt++)
#pragma unroll
            for (int rg = 0; rg < 4; rg++) {
                const int row = row0 + warp_m * 64 + mt * 16 + group + (rg >> 1) * 8;
                const int col = col0 + warp_n * 32 + nt * 8 + tg * 2 + (rg & 1);
                const size_t idx = ((size_t)bh * N_ + row) * N_ + col;
                const bool masked = m4 ? (mask32[idx] != 0u) : (maskp[idx] != 0);
                wout[idx] = masked ? -1e10f : acc[mt][nt][rg] * 0.125f;
            }
}

// ===========================================================================
// Row softmax; writes fp32 weights + bf16 hi/lo copies for attn GEMM.
// ===========================================================================
__global__ void __launch_bounds__(256) softmax_rows(float* __restrict__ w) {
    const size_t base = (size_t)blockIdx.x * N_;
    float* p = w + base;
    float4 v = ((float4*)p)[threadIdx.x];

    __shared__ float smax[8];
    __shared__ float ssum[8];
    const int warp = threadIdx.x >> 5, lane = threadIdx.x & 31;

    float m = fmaxf(fmaxf(v.x, v.y), fmaxf(v.z, v.w));
#pragma unroll
    for (int o = 16; o; o >>= 1) m = fmaxf(m, __shfl_xor_sync(~0u, m, o));
    if (lane == 0) smax[warp] = m;
    __syncthreads();
    if (warp == 0) {
        float t = (lane < 8) ? smax[lane] : -3.4e38f;
#pragma unroll
        for (int o = 4; o; o >>= 1) t = fmaxf(t, __shfl_xor_sync(~0u, t, o));
        if (lane == 0) smax[0] = t;
    }
    __syncthreads();
    m = smax[0];

    v.x = __expf(v.x - m); v.y = __expf(v.y - m);
    v.z = __expf(v.z - m); v.w = __expf(v.w - m);
    float s = v.x + v.y + v.z + v.w;
#pragma unroll
    for (int o = 16; o; o >>= 1) s += __shfl_xor_sync(~0u, s, o);
    if (lane == 0) ssum[warp] = s;
    __syncthreads();
    if (warp == 0) {
        float t = (lane < 8) ? ssum[lane] : 0.0f;
#pragma unroll
        for (int o = 4; o; o >>= 1) t += __shfl_xor_sync(~0u, t, o);
        if (lane == 0) ssum[0] = t;
    }
    __syncthreads();
    const float inv = 1.0f / ssum[0];
    v.x *= inv; v.y *= inv; v.z *= inv; v.w *= inv;
    ((float4*)p)[threadIdx.x] = v;

    __nv_bfloat16 h0 = __float2bfloat16(v.x), h1 = __float2bfloat16(v.y);
    __nv_bfloat16 h2 = __float2bfloat16(v.z), h3 = __float2bfloat16(v.w);
    __nv_bfloat16 l0 = __float2bfloat16(v.x - __bfloat162float(h0));
    __nv_bfloat16 l1 = __float2bfloat16(v.y - __bfloat162float(h1));
    __nv_bfloat16 l2 = __float2bfloat16(v.z - __bfloat162float(h2));
    __nv_bfloat16 l3 = __float2bfloat16(v.w - __bfloat162float(h3));
    const size_t off = base + threadIdx.x * 4;
    *(__nv_bfloat162*)(g_wh + off)     = __nv_bfloat162(h0, h1);
    *(__nv_bfloat162*)(g_wh + off + 2) = __nv_bfloat162(h2, h3);
    *(__nv_bfloat162*)(g_wl + off)     = __nv_bfloat162(l0, l1);
    *(__nv_bfloat162*)(g_wl + off + 2) = __nv_bfloat162(l2, l3);
}

// ===========================================================================
// attn = weights @ v via mma, bf16x3 (3-pass issue order).
// ===========================================================================
#define AT_B   (128 * LDQ * 2)
#define VT_B   (64 * LDQ * 2)
#define AB_B   (2 * AT_B + 2 * VT_B)
#define NKB_A  (N_ / 64)

__global__ void __launch_bounds__(256, 1) attn_mma(void) {
    extern __shared__ char smem[];
    const int tid = threadIdx.x;
    const int wid = tid >> 5;
    const int lane = tid & 31;
    const int warp_m = wid >> 1;
    const int warp_n = wid & 1;
    const int bh = blockIdx.y;
    const int row0 = blockIdx.x * 128;

    const __nv_bfloat16* whb = g_wh + (size_t)bh * N_ * N_;
    const __nv_bfloat16* wlb = g_wl + (size_t)bh * N_ * N_;
    const __nv_bfloat16* vhb = g_vh + (size_t)bh * N_ * DH_;
    const __nv_bfloat16* vlb = g_vl + (size_t)bh * N_ * DH_;

    const int ar = tid >> 1, ahalf = tid & 1;
    const uint32_t a_dst = (uint32_t)ar * (LDQ * 2) + (uint32_t)ahalf * 64;
    const int vr = tid >> 2, vq = tid & 3;
    const uint32_t v_dst = (uint32_t)vr * (LDQ * 2) + (uint32_t)vq * 32;

    {
        const size_t asrc = (size_t)(row0 + ar) * N_ + ahalf * 32;
        const size_t vsrc = (size_t)vr * DH_ + vq * 16;
#pragma unroll
        for (int j = 0; j < 4; j++) {
            *(uint4*)(smem + 0*AT_B + a_dst + j*16) = *(const uint4*)(whb + asrc + j*8);
            *(uint4*)(smem + 1*AT_B + a_dst + j*16) = *(const uint4*)(wlb + asrc + j*8);
        }
#pragma unroll
        for (int j = 0; j < 2; j++) {
            *(uint4*)(smem + 2*AT_B + 0*VT_B + v_dst + j*16) = *(const uint4*)(vhb + vsrc + j*8);
            *(uint4*)(smem + 2*AT_B + 1*VT_B + v_dst + j*16) = *(const uint4*)(vlb + vsrc + j*8);
        }
    }
    __syncthreads();

    const uint32_t sb = smem_u32(smem);
    const int l15 = lane & 15;
    const int a_row = warp_m * 32 + l15;
    const int a_colb = (lane >> 4) * 16;
    const int v_row = l15;
    const int v_colb = (warp_n * 32) * 2 + (lane >> 4) * 16;

    float acc[2][4][4] = {};
    uint4 pa[8], pv[4];

    for (int kb = 0; kb < NKB_A; kb++) {
        if (kb + 1 < NKB_A) {
            const int k0 = (kb + 1) * 64;
            const size_t asrc = (size_t)(row0 + ar) * N_ + k0 + ahalf * 32;
            const size_t vsrc = (size_t)(k0 + vr) * DH_ + vq * 16;
#pragma unroll
            for (int j = 0; j < 4; j++) {
                pa[j]     = *(const uint4*)(whb + asrc + j*8);
                pa[4 + j] = *(const uint4*)(wlb + asrc + j*8);
            }
#pragma unroll
            for (int j = 0; j < 2; j++) {
                pv[j]     = *(const uint4*)(vhb + vsrc + j*8);
                pv[2 + j] = *(const uint4*)(vlb + vsrc + j*8);
            }
        }

        const uint32_t buf = sb + (uint32_t)(kb & 1) * AB_B;
#pragma unroll
        for (int s = 0; s < 4; s++) {
            uint32_t a_hi[2][4], a_lo[2][4], b_hi[4][2], b_lo[4][2];
#pragma unroll
            for (int mt = 0; mt < 2; mt++) {
                const uint32_t off = (uint32_t)(a_row + mt * 16) * (LDQ * 2) + a_colb + s * 32;
                ldsm_x4(a_hi[mt], buf + 0 * AT_B + off);
                ldsm_x4(a_lo[mt], buf + 1 * AT_B + off);
            }
#pragma unroll
            for (int p = 0; p < 2; p++) {
                const uint32_t off = (uint32_t)(s * 16 + v_row) * (LDQ * 2) + v_colb + p * 32;
                uint32_t th[4], tl[4];
                ldsm_x4_t(th, buf + 2 * AT_B + 0 * VT_B + off);
                ldsm_x4_t(tl, buf + 2 * AT_B + 1 * VT_B + off);
                b_hi[2*p][0] = th[0]; b_hi[2*p][1] = th[1];
                b_hi[2*p+1][0] = th[2]; b_hi[2*p+1][1] = th[3];
                b_lo[2*p][0] = tl[0]; b_lo[2*p][1] = tl[1];
                b_lo[2*p+1][0] = tl[2]; b_lo[2*p+1][1] = tl[3];
            }
#pragma unroll
            for (int mt = 0; mt < 2; mt++)
#pragma unroll
                for (int nt = 0; nt < 4; nt++)
                    mma_bf16(acc[mt][nt], a_hi[mt], b_hi[nt]);
#pragma unroll
            for (int mt = 0; mt < 2; mt++)
#pragma unroll
                for (int nt = 0; nt < 4; nt++)
                    mma_bf16(acc[mt][nt], a_lo[mt], b_hi[nt]);
#pragma unroll
            for (int mt = 0; mt < 2; mt++)
#pragma unroll
                for (int nt = 0; nt < 4; nt++)
                    mma_bf16(acc[mt][nt], a_hi[mt], b_lo[nt]);
        }

        if (kb + 1 < NKB_A) {
            char* base = smem + ((kb + 1) & 1) * AB_B;
#pragma unroll
            for (int j = 0; j < 4; j++) {
                *(uint4*)(base + 0*AT_B + a_dst + j*16) = pa[j];
                *(uint4*)(base + 1*AT_B + a_dst + j*16) = pa[4 + j];
            }
#pragma unroll
            for (int j = 0; j < 2; j++) {
                *(uint4*)(base + 2*AT_B + 0*VT_B + v_dst + j*16) = pv[j];
                *(uint4*)(base + 2*AT_B + 1*VT_B + v_dst + j*16) = pv[2 + j];
            }
        }
        __syncthreads();
    }

    const int b = bh >> 4;
    const int h = bh & (H_ - 1);
    const int group = lane >> 2, tg = lane & 3;
#pragma unroll
    for (int mt = 0; mt < 2; mt++)
#pragma unroll
        for (int nt = 0; nt < 4; nt++)
#pragma unroll
            for (int rp = 0; rp < 2; rp++) {
                const int n = row0 + warp_m * 32 + mt * 16 + group + rp * 8;
                const int dh = warp_n * 32 + nt * 8 + tg * 2;
                float* dst = &g_attn[((size_t)b * N_ + n) * D_ + h * DH_ + dh];
                dst[0] = acc[mt][nt][rp * 2 + 0];
                dst[1] = acc[mt][nt][rp * 2 + 1];
            }
}

// ===========================================================================
extern "C" void kernel_launch(void* const* d_in, const int* in_sizes, int n_in,
                              void* d_out, int out_size) {
    const float* Q  = (const float*)d_in[0];
    const float* K  = (const float*)d_in[1];
    const float* V  = (const float*)d_in[2];
    const unsigned char* mask = (const unsigned char*)d_in[3];
    const float* Wq = (const float*)d_in[4];
    const float* bq = (const float*)d_in[5];
    const float* Wk = (const float*)d_in[6];
    const float* bk = (const float*)d_in[7];
    const float* Wv = (const float*)d_in[8];
    const float* bv = (const float*)d_in[9];
    const float* Wo = (const float*)d_in[10];
    const float* bo = (const float*)d_in[11];

    float* xout = (float*)d_out;
    float* wout = xout + (size_t)M_ * D_;

    __nv_bfloat16 *qh, *ql, *kh, *kl, *vh, *vl;
    float* ap;
    cudaGetSymbolAddress((void**)&qh, g_qh);
    cudaGetSymbolAddress((void**)&ql, g_ql);
    cudaGetSymbolAddress((void**)&kh, g_kh);
    cudaGetSymbolAddress((void**)&kl, g_kl);
    cudaGetSymbolAddress((void**)&vh, g_vh);
    cudaGetSymbolAddress((void**)&vl, g_vl);
    cudaGetSymbolAddress((void**)&ap, g_attn);

    const int gemm_smem = 2 * BUF_B;
    const int scores_smem = 4 * QT_B;
    const int attn_smem = 2 * AB_B;
    cudaFuncSetAttribute(gemm_mma<0>, cudaFuncAttributeMaxDynamicSharedMemorySize, gemm_smem);
    cudaFuncSetAttribute(gemm_mma<1>, cudaFuncAttributeMaxDynamicSharedMemorySize, gemm_smem);
    cudaFuncSetAttribute(scores_mma, cudaFuncAttributeMaxDynamicSharedMemorySize, scores_smem);
    cudaFuncSetAttribute(attn_mma, cudaFuncAttributeMaxDynamicSharedMemorySize, attn_smem);

    detect_mask_kind<<<1, 256>>>(mask);

    dim3 gp(D_ / 128, M_ / 128);
    gemm_mma<1><<<gp, 256, gemm_smem>>>(Q, Wq, bq, nullptr, qh, ql);
    gemm_mma<1><<<gp, 256, gemm_smem>>>(K, Wk, bk, nullptr, kh, kl);
    gemm_mma<1><<<gp, 256, gemm_smem>>>(V, Wv, bv, nullptr, vh, vl);

    scores_mma<<<dim3(N_ / 128, N_ / 128, BH_), 256, scores_smem>>>(mask, wout);
    softmax_rows<<<BH_ * N_, 256>>>(wout);
    attn_mma<<<dim3(N_ / 128, BH_), 256, attn_smem>>>();

    gemm_mma<0><<<gp, 256, gemm_smem>>>(ap, Wo, bo, xout, nullptr, nullptr);
}

// round 6
// speedup vs baseline: 2.1985x; 1.0769x over previous
#include <cuda_runtime.h>
#include <cuda_bf16.h>
#include <cstdint>

// Problem constants
#define B_   4
#define N_   1024
#define D_   1024
#define H_   16
#define DH_  64
#define M_   (B_ * N_)    // 4096
#define BH_  (B_ * H_)    // 64

// Scratch (allocation-free rule: __device__ globals)
__device__ __nv_bfloat16 g_qh[(size_t)BH_ * N_ * DH_];
__device__ __nv_bfloat16 g_ql[(size_t)BH_ * N_ * DH_];
__device__ __nv_bfloat16 g_kh[(size_t)BH_ * N_ * DH_];
__device__ __nv_bfloat16 g_kl[(size_t)BH_ * N_ * DH_];
__device__ __nv_bfloat16 g_vh[(size_t)BH_ * N_ * DH_];
__device__ __nv_bfloat16 g_vl[(size_t)BH_ * N_ * DH_];
__device__ __nv_bfloat16 g_wh[(size_t)BH_ * N_ * N_];
__device__ __nv_bfloat16 g_wl[(size_t)BH_ * N_ * N_];
// pre-converted inputs (Q,K,V) and weights (Wq,Wk,Wv,Wo), bf16 hi/lo
__device__ __nv_bfloat16 g_inh[3][(size_t)M_ * D_];
__device__ __nv_bfloat16 g_inl[3][(size_t)M_ * D_];
__device__ __nv_bfloat16 g_wth[4][(size_t)D_ * D_];
__device__ __nv_bfloat16 g_wtl[4][(size_t)D_ * D_];
// attention output in bf16 hi/lo [b,n,d]
__device__ __nv_bfloat16 g_ah[(size_t)M_ * D_];
__device__ __nv_bfloat16 g_al[(size_t)M_ * D_];
__device__ int   g_mask4;

// ===========================================================================
// Helpers (generic PTX, sm_80+ only)
// ===========================================================================
__device__ __forceinline__ uint32_t smem_u32(const void* p) {
    uint32_t a;
    asm("{ .reg .u64 t; cvta.to.shared.u64 t, %1; cvt.u32.u64 %0, t; }" : "=r"(a) : "l"(p));
    return a;
}
__device__ __forceinline__ void ldsm_x4(uint32_t* r, uint32_t addr) {
    asm volatile("ldmatrix.sync.aligned.m8n8.x4.shared.b16 {%0,%1,%2,%3}, [%4];"
                 : "=r"(r[0]), "=r"(r[1]), "=r"(r[2]), "=r"(r[3]) : "r"(addr));
}
__device__ __forceinline__ void ldsm_x4_t(uint32_t* r, uint32_t addr) {
    asm volatile("ldmatrix.sync.aligned.m8n8.x4.trans.shared.b16 {%0,%1,%2,%3}, [%4];"
                 : "=r"(r[0]), "=r"(r[1]), "=r"(r[2]), "=r"(r[3]) : "r"(addr));
}
__device__ __forceinline__ void mma_bf16(float* c, const uint32_t* a, const uint32_t* b) {
    asm volatile(
        "mma.sync.aligned.m16n8k16.row.col.f32.bf16.bf16.f32 "
        "{%0,%1,%2,%3}, {%4,%5,%6,%7}, {%8,%9}, {%0,%1,%2,%3};"
        : "+f"(c[0]), "+f"(c[1]), "+f"(c[2]), "+f"(c[3])
        : "r"(a[0]), "r"(a[1]), "r"(a[2]), "r"(a[3]), "r"(b[0]), "r"(b[1]));
}
__device__ __forceinline__ void cp16(uint32_t smem, const void* g) {
    asm volatile("cp.async.ca.shared.global [%0], [%1], 16;" :: "r"(smem), "l"(g));
}
__device__ __forceinline__ void cp_commit() { asm volatile("cp.async.commit_group;"); }
template <int N>
__device__ __forceinline__ void cp_wait() { asm volatile("cp.async.wait_group %0;" :: "n"(N)); }

// ===========================================================================
// One-time fp32 -> bf16 hi/lo conversion (elementwise, memory-bound)
// ===========================================================================
__global__ void cvt_hilo(const float* __restrict__ src,
                         __nv_bfloat16* __restrict__ dh,
                         __nv_bfloat16* __restrict__ dl, int n4) {
    const int i = blockIdx.x * blockDim.x + threadIdx.x;
    if (i >= n4) return;
    float4 v = ((const float4*)src)[i];
    __nv_bfloat16 h0 = __float2bfloat16(v.x), h1 = __float2bfloat16(v.y);
    __nv_bfloat16 h2 = __float2bfloat16(v.z), h3 = __float2bfloat16(v.w);
    __nv_bfloat16 l0 = __float2bfloat16(v.x - __bfloat162float(h0));
    __nv_bfloat16 l1 = __float2bfloat16(v.y - __bfloat162float(h1));
    __nv_bfloat16 l2 = __float2bfloat16(v.z - __bfloat162float(h2));
    __nv_bfloat16 l3 = __float2bfloat16(v.w - __bfloat162float(h3));
    ((__nv_bfloat162*)dh)[i * 2]     = __nv_bfloat162(h0, h1);
    ((__nv_bfloat162*)dh)[i * 2 + 1] = __nv_bfloat162(h2, h3);
    ((__nv_bfloat162*)dl)[i * 2]     = __nv_bfloat162(l0, l1);
    ((__nv_bfloat162*)dl)[i * 2 + 1] = __nv_bfloat162(l2, l3);
}

// ===========================================================================
// bf16x3 NT GEMM, all operands pre-converted bf16 hi/lo, cp.async staging.
// C[4096 x 1024] = A @ W^T + bias, K = 1024. CTA 128x128, BK=32, 8 warps.
// MODE 0: fp32 row-major out. MODE 1: bf16 hi/lo head-split out [b,h,n,dh].
// ===========================================================================
#define BK_      32
#define LDS_     40                         // bf16 per padded row (80B)
#define TILE_B   (128 * LDS_ * 2)           // 10240 B
#define BUF_B    (4 * TILE_B)               // Ahi, Alo, Bhi, Blo = 40960 B
#define NUM_KB   (D_ / BK_)                 // 32

template <int MODE>
__global__ void __launch_bounds__(256, 1) gemm_mma(const __nv_bfloat16* __restrict__ Ah,
                                                   const __nv_bfloat16* __restrict__ Al,
                                                   const __nv_bfloat16* __restrict__ Bh,
                                                   const __nv_bfloat16* __restrict__ Bl,
                                                   const float* __restrict__ bias,
                                                   float* __restrict__ C,
                                                   __nv_bfloat16* __restrict__ Chi,
                                                   __nv_bfloat16* __restrict__ Clo) {
    extern __shared__ char smem[];
    __shared__ float s_bias[128];

    const int tid = threadIdx.x;
    const int wid = tid >> 5;
    const int lane = tid & 31;
    const int warp_m = wid >> 2;
    const int warp_n = wid & 3;
    const int row0 = blockIdx.y * 128;
    const int col0 = blockIdx.x * 128;

    if (tid < 128) s_bias[tid] = bias[col0 + tid];

    // cp.async mapping: thread covers row r, half h (32 bf16 = 64B per row; 2x16B per half)
    const int r  = tid >> 1;
    const int half = tid & 1;
    const __nv_bfloat16* Ah_p = Ah + (size_t)(row0 + r) * D_ + half * 16;
    const __nv_bfloat16* Al_p = Al + (size_t)(row0 + r) * D_ + half * 16;
    const __nv_bfloat16* Bh_p = Bh + (size_t)(col0 + r) * D_ + half * 16;
    const __nv_bfloat16* Bl_p = Bl + (size_t)(col0 + r) * D_ + half * 16;
    const uint32_t sb = smem_u32(smem);
    const uint32_t st = sb + (uint32_t)r * (LDS_ * 2) + (uint32_t)half * 32;

    // ldmatrix lane addressing
    const int seg = lane >> 3, l7 = lane & 7;
    const int a_row = warp_m * 64 + (seg & 1) * 8 + l7;
    const int a_colb = (((seg >> 1) & 1) * 8) * 2;
    const int b_row = warp_n * 32 + ((seg >> 1) & 1) * 8 + l7;
    const int b_colb = ((seg & 1) * 8) * 2;

    float acc[4][4][4] = {};

    // prologue: stage k-block 0 into buffer 0
    {
        cp16(st + 0*TILE_B,      Ah_p);
        cp16(st + 0*TILE_B + 16, Ah_p + 8);    // +8 bf16 = +16B? no: +16B = 8 elems
        cp16(st + 1*TILE_B,      Al_p);
        cp16(st + 1*TILE_B + 16, Al_p + 8);
        cp16(st + 2*TILE_B,      Bh_p);
        cp16(st + 2*TILE_B + 16, Bh_p + 8);
        cp16(st + 3*TILE_B,      Bl_p);
        cp16(st + 3*TILE_B + 16, Bl_p + 8);
        cp_commit();
    }

    for (int kb = 0; kb < NUM_KB; kb++) {
        // stage next k-block into the other buffer
        if (kb + 1 < NUM_KB) {
            const int k0 = (kb + 1) * BK_;
            const uint32_t nst = st + (uint32_t)((kb + 1) & 1) * BUF_B;
            cp16(nst + 0*TILE_B,      Ah_p + k0);
            cp16(nst + 0*TILE_B + 16, Ah_p + k0 + 8);
            cp16(nst + 1*TILE_B,      Al_p + k0);
            cp16(nst + 1*TILE_B + 16, Al_p + k0 + 8);
            cp16(nst + 2*TILE_B,      Bh_p + k0);
            cp16(nst + 2*TILE_B + 16, Bh_p + k0 + 8);
            cp16(nst + 3*TILE_B,      Bl_p + k0);
            cp16(nst + 3*TILE_B + 16, Bl_p + k0 + 8);
            cp_commit();
            cp_wait<1>();
        } else {
            cp_wait<0>();
        }
        __syncthreads();

        const uint32_t buf = sb + (uint32_t)(kb & 1) * BUF_B;
#pragma unroll
        for (int s = 0; s < 2; s++) {
            uint32_t a_hi[4][4], a_lo[4][4], b_hi[4][2], b_lo[4][2];
#pragma unroll
            for (int mt = 0; mt < 4; mt++) {
                const uint32_t off = (uint32_t)(a_row + mt * 16) * (LDS_ * 2) + a_colb + s * 32;
                ldsm_x4(a_hi[mt], buf + 0 * TILE_B + off);
                ldsm_x4(a_lo[mt], buf + 1 * TILE_B + off);
            }
#pragma unroll
            for (int p = 0; p < 2; p++) {
                const uint32_t off = (uint32_t)(b_row + p * 16) * (LDS_ * 2) + b_colb + s * 32;
                uint32_t th[4], tl[4];
                ldsm_x4(th, buf + 2 * TILE_B + off);
                ldsm_x4(tl, buf + 3 * TILE_B + off);
                b_hi[2*p][0] = th[0]; b_hi[2*p][1] = th[1];
                b_hi[2*p+1][0] = th[2]; b_hi[2*p+1][1] = th[3];
                b_lo[2*p][0] = tl[0]; b_lo[2*p][1] = tl[1];
                b_lo[2*p+1][0] = tl[2]; b_lo[2*p+1][1] = tl[3];
            }
#pragma unroll
            for (int mt = 0; mt < 4; mt++)
#pragma unroll
                for (int nt = 0; nt < 4; nt++) {
                    mma_bf16(acc[mt][nt], a_hi[mt], b_hi[nt]);
                    mma_bf16(acc[mt][nt], a_lo[mt], b_hi[nt]);
                    mma_bf16(acc[mt][nt], a_hi[mt], b_lo[nt]);
                }
        }
        __syncthreads();
    }

    const int group = lane >> 2, tg = lane & 3;
#pragma unroll
    for (int mt = 0; mt < 4; mt++) {
#pragma unroll
        for (int nt = 0; nt < 4; nt++) {
#pragma unroll
            for (int rp = 0; rp < 2; rp++) {
                const int row = row0 + warp_m * 64 + mt * 16 + group + rp * 8;
                const int lcol = warp_n * 32 + nt * 8 + tg * 2;
                const float v0 = acc[mt][nt][rp * 2 + 0] + s_bias[lcol];
                const float v1 = acc[mt][nt][rp * 2 + 1] + s_bias[lcol + 1];
                if (MODE == 0) {
                    C[(size_t)row * D_ + col0 + lcol] = v0;
                    C[(size_t)row * D_ + col0 + lcol + 1] = v1;
                } else {
                    const int b = row >> 10;
                    const int n = row & (N_ - 1);
                    const int col = col0 + lcol;
                    const int h = col >> 6;
                    const int dh = col & (DH_ - 1);
                    const size_t idx = (((size_t)b * H_ + h) * N_ + n) * DH_ + dh;
                    __nv_bfloat16 h0 = __float2bfloat16(v0);
                    __nv_bfloat16 h1 = __float2bfloat16(v1);
                    __nv_bfloat16 l0 = __float2bfloat16(v0 - __bfloat162float(h0));
                    __nv_bfloat16 l1 = __float2bfloat16(v1 - __bfloat162float(h1));
                    *(__nv_bfloat162*)(Chi + idx) = __nv_bfloat162(h0, h1);
                    *(__nv_bfloat162*)(Clo + idx) = __nv_bfloat162(l0, l1);
                }
            }
        }
    }
}

// ===========================================================================
// Mask dtype detection (unchanged)
// ===========================================================================
__global__ void detect_mask_kind(const unsigned char* __restrict__ m) {
    __shared__ int has_gt1, has_mis;
    if (threadIdx.x == 0) { has_gt1 = 0; has_mis = 0; }
    __syncthreads();
    int lg = 0, lm = 0;
    for (int i = threadIdx.x * 16; i < 65536; i += blockDim.x * 16) {
        uint4 v = *(const uint4*)(m + i);
        unsigned int w[4] = {v.x, v.y, v.z, v.w};
#pragma unroll
        for (int j = 0; j < 4; j++) {
#pragma unroll
            for (int b = 0; b < 4; b++) {
                unsigned int byte = (w[j] >> (8 * b)) & 0xFFu;
                int pos = i + j * 4 + b;
                if (byte > 1u) lg = 1;
                if (byte != 0u && (pos & 3)) lm = 1;
            }
        }
    }
    if (lg) atomicOr(&has_gt1, 1);
    if (lm) atomicOr(&has_mis, 1);
    __syncthreads();
    if (threadIdx.x == 0) g_mask4 = (has_gt1 || !has_mis) ? 1 : 0;
}

// ===========================================================================
// Scores via mma, bf16x3: S = q @ k^T / 8, masked. (unchanged)
// ===========================================================================
#define LDQ  72
#define QT_B (128 * LDQ * 2)

__global__ void __launch_bounds__(256, 1) scores_mma(const unsigned char* __restrict__ maskp,
                                                     float* __restrict__ wout) {
    extern __shared__ char smem[];
    const int tid = threadIdx.x;
    const int wid = tid >> 5;
    const int lane = tid & 31;
    const int warp_m = wid >> 2;
    const int warp_n = wid & 3;
    const int bh = blockIdx.z;
    const int row0 = blockIdx.y * 128;
    const int col0 = blockIdx.x * 128;

    const int r = tid >> 1;
    const int half = tid & 1;
    const size_t qsrc = (size_t)bh * N_ * DH_ + (size_t)(row0 + r) * DH_ + half * 32;
    const size_t ksrc = (size_t)bh * N_ * DH_ + (size_t)(col0 + r) * DH_ + half * 32;
    const uint32_t dst = (uint32_t)r * (LDQ * 2) + (uint32_t)half * 64;
#pragma unroll
    for (int j = 0; j < 4; j++) {
        *(uint4*)(smem + 0*QT_B + dst + j*16) = *(const uint4*)(g_qh + qsrc + j*8);
        *(uint4*)(smem + 1*QT_B + dst + j*16) = *(const uint4*)(g_ql + qsrc + j*8);
        *(uint4*)(smem + 2*QT_B + dst + j*16) = *(const uint4*)(g_kh + ksrc + j*8);
        *(uint4*)(smem + 3*QT_B + dst + j*16) = *(const uint4*)(g_kl + ksrc + j*8);
    }
    __syncthreads();

    const uint32_t sb = smem_u32(smem);
    const int seg = lane >> 3, l7 = lane & 7;
    const int a_row = warp_m * 64 + (seg & 1) * 8 + l7;
    const int a_colb = (((seg >> 1) & 1) * 8) * 2;
    const int b_row = warp_n * 32 + ((seg >> 1) & 1) * 8 + l7;
    const int b_colb = ((seg & 1) * 8) * 2;

    float acc[4][4][4] = {};
#pragma unroll
    for (int s = 0; s < 4; s++) {
        uint32_t a_hi[4][4], a_lo[4][4], b_hi[4][2], b_lo[4][2];
#pragma unroll
        for (int mt = 0; mt < 4; mt++) {
            const uint32_t off = (uint32_t)(a_row + mt * 16) * (LDQ * 2) + a_colb + s * 32;
            ldsm_x4(a_hi[mt], sb + 0 * QT_B + off);
            ldsm_x4(a_lo[mt], sb + 1 * QT_B + off);
        }
#pragma unroll
        for (int p = 0; p < 2; p++) {
            const uint32_t off = (uint32_t)(b_row + p * 16) * (LDQ * 2) + b_colb + s * 32;
            uint32_t th[4], tl[4];
            ldsm_x4(th, sb + 2 * QT_B + off);
            ldsm_x4(tl, sb + 3 * QT_B + off);
            b_hi[2*p][0] = th[0]; b_hi[2*p][1] = th[1];
            b_hi[2*p+1][0] = th[2]; b_hi[2*p+1][1] = th[3];
            b_lo[2*p][0] = tl[0]; b_lo[2*p][1] = tl[1];
            b_lo[2*p+1][0] = tl[2]; b_lo[2*p+1][1] = tl[3];
        }
#pragma unroll
        for (int mt = 0; mt < 4; mt++)
#pragma unroll
            for (int nt = 0; nt < 4; nt++) {
                mma_bf16(acc[mt][nt], a_hi[mt], b_hi[nt]);
                mma_bf16(acc[mt][nt], a_lo[mt], b_hi[nt]);
                mma_bf16(acc[mt][nt], a_hi[mt], b_lo[nt]);
            }
    }

    const int group = lane >> 2, tg = lane & 3;
    const int m4 = g_mask4;
    const unsigned int* mask32 = (const unsigned int*)maskp;
#pragma unroll
    for (int mt = 0; mt < 4; mt++)
#pragma unroll
        for (int nt = 0; nt < 4; nt++)
#pragma unroll
            for (int rg = 0; rg < 4; rg++) {
                const int row = row0 + warp_m * 64 + mt * 16 + group + (rg >> 1) * 8;
                const int col = col0 + warp_n * 32 + nt * 8 + tg * 2 + (rg & 1);
                const size_t idx = ((size_t)bh * N_ + row) * N_ + col;
                const bool masked = m4 ? (mask32[idx] != 0u) : (maskp[idx] != 0);
                wout[idx] = masked ? -1e10f : acc[mt][nt][rg] * 0.125f;
            }
}

// ===========================================================================
// Row softmax; writes fp32 weights + bf16 hi/lo copies. (unchanged)
// ===========================================================================
__global__ void __launch_bounds__(256) softmax_rows(float* __restrict__ w) {
    const size_t base = (size_t)blockIdx.x * N_;
    float* p = w + base;
    float4 v = ((float4*)p)[threadIdx.x];

    __shared__ float smax[8];
    __shared__ float ssum[8];
    const int warp = threadIdx.x >> 5, lane = threadIdx.x & 31;

    float m = fmaxf(fmaxf(v.x, v.y), fmaxf(v.z, v.w));
#pragma unroll
    for (int o = 16; o; o >>= 1) m = fmaxf(m, __shfl_xor_sync(~0u, m, o));
    if (lane == 0) smax[warp] = m;
    __syncthreads();
    if (warp == 0) {
        float t = (lane < 8) ? smax[lane] : -3.4e38f;
#pragma unroll
        for (int o = 4; o; o >>= 1) t = fmaxf(t, __shfl_xor_sync(~0u, t, o));
        if (lane == 0) smax[0] = t;
    }
    __syncthreads();
    m = smax[0];

    v.x = __expf(v.x - m); v.y = __expf(v.y - m);
    v.z = __expf(v.z - m); v.w = __expf(v.w - m);
    float s = v.x + v.y + v.z + v.w;
#pragma unroll
    for (int o = 16; o; o >>= 1) s += __shfl_xor_sync(~0u, s, o);
    if (lane == 0) ssum[warp] = s;
    __syncthreads();
    if (warp == 0) {
        float t = (lane < 8) ? ssum[lane] : 0.0f;
#pragma unroll
        for (int o = 4; o; o >>= 1) t += __shfl_xor_sync(~0u, t, o);
        if (lane == 0) ssum[0] = t;
    }
    __syncthreads();
    const float inv = 1.0f / ssum[0];
    v.x *= inv; v.y *= inv; v.z *= inv; v.w *= inv;
    ((float4*)p)[threadIdx.x] = v;

    __nv_bfloat16 h0 = __float2bfloat16(v.x), h1 = __float2bfloat16(v.y);
    __nv_bfloat16 h2 = __float2bfloat16(v.z), h3 = __float2bfloat16(v.w);
    __nv_bfloat16 l0 = __float2bfloat16(v.x - __bfloat162float(h0));
    __nv_bfloat16 l1 = __float2bfloat16(v.y - __bfloat162float(h1));
    __nv_bfloat16 l2 = __float2bfloat16(v.z - __bfloat162float(h2));
    __nv_bfloat16 l3 = __float2bfloat16(v.w - __bfloat162float(h3));
    const size_t off = base + threadIdx.x * 4;
    *(__nv_bfloat162*)(g_wh + off)     = __nv_bfloat162(h0, h1);
    *(__nv_bfloat162*)(g_wh + off + 2) = __nv_bfloat162(h2, h3);
    *(__nv_bfloat162*)(g_wl + off)     = __nv_bfloat162(l0, l1);
    *(__nv_bfloat162*)(g_wl + off + 2) = __nv_bfloat162(l2, l3);
}

// ===========================================================================
// attn = weights @ v via mma, bf16x3; epilogue now emits bf16 hi/lo [b,n,d].
// ===========================================================================
#define AT_B   (128 * LDQ * 2)
#define VT_B   (64 * LDQ * 2)
#define AB_B   (2 * AT_B + 2 * VT_B)
#define NKB_A  (N_ / 64)

__global__ void __launch_bounds__(256, 1) attn_mma(void) {
    extern __shared__ char smem[];
    const int tid = threadIdx.x;
    const int wid = tid >> 5;
    const int lane = tid & 31;
    const int warp_m = wid >> 1;
    const int warp_n = wid & 1;
    const int bh = blockIdx.y;
    const int row0 = blockIdx.x * 128;

    const __nv_bfloat16* whb = g_wh + (size_t)bh * N_ * N_;
    const __nv_bfloat16* wlb = g_wl + (size_t)bh * N_ * N_;
    const __nv_bfloat16* vhb = g_vh + (size_t)bh * N_ * DH_;
    const __nv_bfloat16* vlb = g_vl + (size_t)bh * N_ * DH_;

    const int ar = tid >> 1, ahalf = tid & 1;
    const uint32_t a_dst = (uint32_t)ar * (LDQ * 2) + (uint32_t)ahalf * 64;
    const int vr = tid >> 2, vq = tid & 3;
    const uint32_t v_dst = (uint32_t)vr * (LDQ * 2) + (uint32_t)vq * 32;

    {
        const size_t asrc = (size_t)(row0 + ar) * N_ + ahalf * 32;
        const size_t vsrc = (size_t)vr * DH_ + vq * 16;
#pragma unroll
        for (int j = 0; j < 4; j++) {
            *(uint4*)(smem + 0*AT_B + a_dst + j*16) = *(const uint4*)(whb + asrc + j*8);
            *(uint4*)(smem + 1*AT_B + a_dst + j*16) = *(const uint4*)(wlb + asrc + j*8);
        }
#pragma unroll
        for (int j = 0; j < 2; j++) {
            *(uint4*)(smem + 2*AT_B + 0*VT_B + v_dst + j*16) = *(const uint4*)(vhb + vsrc + j*8);
            *(uint4*)(smem + 2*AT_B + 1*VT_B + v_dst + j*16) = *(const uint4*)(vlb + vsrc + j*8);
        }
    }
    __syncthreads();

    const uint32_t sb = smem_u32(smem);
    const int l15 = lane & 15;
    const int a_row = warp_m * 32 + l15;
    const int a_colb = (lane >> 4) * 16;
    const int v_row = l15;
    const int v_colb = (warp_n * 32) * 2 + (lane >> 4) * 16;

    float acc[2][4][4] = {};
    uint4 pa[8], pv[4];

    for (int kb = 0; kb < NKB_A; kb++) {
        if (kb + 1 < NKB_A) {
            const int k0 = (kb + 1) * 64;
            const size_t asrc = (size_t)(row0 + ar) * N_ + k0 + ahalf * 32;
            const size_t vsrc = (size_t)(k0 + vr) * DH_ + vq * 16;
#pragma unroll
            for (int j = 0; j < 4; j++) {
                pa[j]     = *(const uint4*)(whb + asrc + j*8);
                pa[4 + j] = *(const uint4*)(wlb + asrc + j*8);
            }
#pragma unroll
            for (int j = 0; j < 2; j++) {
                pv[j]     = *(const uint4*)(vhb + vsrc + j*8);
                pv[2 + j] = *(const uint4*)(vlb + vsrc + j*8);
            }
        }

        const uint32_t buf = sb + (uint32_t)(kb & 1) * AB_B;
#pragma unroll
        for (int s = 0; s < 4; s++) {
            uint32_t a_hi[2][4], a_lo[2][4], b_hi[4][2], b_lo[4][2];
#pragma unroll
            for (int mt = 0; mt < 2; mt++) {
                const uint32_t off = (uint32_t)(a_row + mt * 16) * (LDQ * 2) + a_colb + s * 32;
                ldsm_x4(a_hi[mt], buf + 0 * AT_B + off);
                ldsm_x4(a_lo[mt], buf + 1 * AT_B + off);
            }
#pragma unroll
            for (int p = 0; p < 2; p++) {
                const uint32_t off = (uint32_t)(s * 16 + v_row) * (LDQ * 2) + v_colb + p * 32;
                uint32_t th[4], tl[4];
                ldsm_x4_t(th, buf + 2 * AT_B + 0 * VT_B + off);
                ldsm_x4_t(tl, buf + 2 * AT_B + 1 * VT_B + off);
                b_hi[2*p][0] = th[0]; b_hi[2*p][1] = th[1];
                b_hi[2*p+1][0] = th[2]; b_hi[2*p+1][1] = th[3];
                b_lo[2*p][0] = tl[0]; b_lo[2*p][1] = tl[1];
                b_lo[2*p+1][0] = tl[2]; b_lo[2*p+1][1] = tl[3];
            }
#pragma unroll
            for (int mt = 0; mt < 2; mt++)
#pragma unroll
                for (int nt = 0; nt < 4; nt++) {
                    mma_bf16(acc[mt][nt], a_hi[mt], b_hi[nt]);
                    mma_bf16(acc[mt][nt], a_lo[mt], b_hi[nt]);
                    mma_bf16(acc[mt][nt], a_hi[mt], b_lo[nt]);
                }
        }

        if (kb + 1 < NKB_A) {
            char* base = smem + ((kb + 1) & 1) * AB_B;
#pragma unroll
            for (int j = 0; j < 4; j++) {
                *(uint4*)(base + 0*AT_B + a_dst + j*16) = pa[j];
                *(uint4*)(base + 1*AT_B + a_dst + j*16) = pa[4 + j];
            }
#pragma unroll
            for (int j = 0; j < 2; j++) {
                *(uint4*)(base + 2*AT_B + 0*VT_B + v_dst + j*16) = pv[j];
                *(uint4*)(base + 2*AT_B + 1*VT_B + v_dst + j*16) = pv[2 + j];
            }
        }
        __syncthreads();
    }

    const int b = bh >> 4;
    const int h = bh & (H_ - 1);
    const int group = lane >> 2, tg = lane & 3;
#pragma unroll
    for (int mt = 0; mt < 2; mt++)
#pragma unroll
        for (int nt = 0; nt < 4; nt++)
#pragma unroll
            for (int rp = 0; rp < 2; rp++) {
                const int n = row0 + warp_m * 32 + mt * 16 + group + rp * 8;
                const int dh = warp_n * 32 + nt * 8 + tg * 2;
                const float v0 = acc[mt][nt][rp * 2 + 0];
                const float v1 = acc[mt][nt][rp * 2 + 1];
                const size_t idx = ((size_t)b * N_ + n) * D_ + h * DH_ + dh;
                __nv_bfloat16 h0 = __float2bfloat16(v0);
                __nv_bfloat16 h1 = __float2bfloat16(v1);
                __nv_bfloat16 l0 = __float2bfloat16(v0 - __bfloat162float(h0));
                __nv_bfloat16 l1 = __float2bfloat16(v1 - __bfloat162float(h1));
                *(__nv_bfloat162*)(g_ah + idx) = __nv_bfloat162(h0, h1);
                *(__nv_bfloat162*)(g_al + idx) = __nv_bfloat162(l0, l1);
            }
}

// ===========================================================================
extern "C" void kernel_launch(void* const* d_in, const int* in_sizes, int n_in,
                              void* d_out, int out_size) {
    const float* Q  = (const float*)d_in[0];
    const float* K  = (const float*)d_in[1];
    const float* V  = (const float*)d_in[2];
    const unsigned char* mask = (const unsigned char*)d_in[3];
    const float* Wq = (const float*)d_in[4];
    const float* bq = (const float*)d_in[5];
    const float* Wk = (const float*)d_in[6];
    const float* bk = (const float*)d_in[7];
    const float* Wv = (const float*)d_in[8];
    const float* bv = (const float*)d_in[9];
    const float* Wo = (const float*)d_in[10];
    const float* bo = (const float*)d_in[11];

    float* xout = (float*)d_out;
    float* wout = xout + (size_t)M_ * D_;

    __nv_bfloat16 *qh, *ql, *kh, *kl, *vh, *vl, *inh, *inl, *wth, *wtl, *ah, *al;
    cudaGetSymbolAddress((void**)&qh, g_qh);
    cudaGetSymbolAddress((void**)&ql, g_ql);
    cudaGetSymbolAddress((void**)&kh, g_kh);
    cudaGetSymbolAddress((void**)&kl, g_kl);
    cudaGetSymbolAddress((void**)&vh, g_vh);
    cudaGetSymbolAddress((void**)&vl, g_vl);
    cudaGetSymbolAddress((void**)&inh, g_inh);
    cudaGetSymbolAddress((void**)&inl, g_inl);
    cudaGetSymbolAddress((void**)&wth, g_wth);
    cudaGetSymbolAddress((void**)&wtl, g_wtl);
    cudaGetSymbolAddress((void**)&ah, g_ah);
    cudaGetSymbolAddress((void**)&al, g_al);

    const int gemm_smem = 2 * BUF_B;
    const int scores_smem = 4 * QT_B;
    const int attn_smem = 2 * AB_B;
    cudaFuncSetAttribute(gemm_mma<0>, cudaFuncAttributeMaxDynamicSharedMemorySize, gemm_smem);
    cudaFuncSetAttribute(gemm_mma<1>, cudaFuncAttributeMaxDynamicSharedMemorySize, gemm_smem);
    cudaFuncSetAttribute(scores_mma, cudaFuncAttributeMaxDynamicSharedMemorySize, scores_smem);
    cudaFuncSetAttribute(attn_mma, cudaFuncAttributeMaxDynamicSharedMemorySize, attn_smem);

    detect_mask_kind<<<1, 256>>>(mask);

    // pre-convert inputs + weights to bf16 hi/lo
    const size_t inN = (size_t)M_ * D_;   // 4M
    const size_t wN  = (size_t)D_ * D_;   // 1M
    cvt_hilo<<<(int)(inN / 4 / 256), 256>>>(Q, inh + 0 * inN, inl + 0 * inN, (int)(inN / 4));
    cvt_hilo<<<(int)(inN / 4 / 256), 256>>>(K, inh + 1 * inN, inl + 1 * inN, (int)(inN / 4));
    cvt_hilo<<<(int)(inN / 4 / 256), 256>>>(V, inh + 2 * inN, inl + 2 * inN, (int)(inN / 4));
    cvt_hilo<<<(int)(wN / 4 / 256), 256>>>(Wq, wth + 0 * wN, wtl + 0 * wN, (int)(wN / 4));
    cvt_hilo<<<(int)(wN / 4 / 256), 256>>>(Wk, wth + 1 * wN, wtl + 1 * wN, (int)(wN / 4));
    cvt_hilo<<<(int)(wN / 4 / 256), 256>>>(Wv, wth + 2 * wN, wtl + 2 * wN, (int)(wN / 4));
    cvt_hilo<<<(int)(wN / 4 / 256), 256>>>(Wo, wth + 3 * wN, wtl + 3 * wN, (int)(wN / 4));

    dim3 gp(D_ / 128, M_ / 128);
    gemm_mma<1><<<gp, 256, gemm_smem>>>(inh + 0*inN, inl + 0*inN, wth + 0*wN, wtl + 0*wN, bq, nullptr, qh, ql);
    gemm_mma<1><<<gp, 256, gemm_smem>>>(inh + 1*inN, inl + 1*inN, wth + 1*wN, wtl + 1*wN, bk, nullptr, kh, kl);
    gemm_mma<1><<<gp, 256, gemm_smem>>>(inh + 2*inN, inl + 2*inN, wth + 2*wN, wtl + 2*wN, bv, nullptr, vh, vl);

    scores_mma<<<dim3(N_ / 128, N_ / 128, BH_), 256, scores_smem>>>(mask, wout);
    softmax_rows<<<BH_ * N_, 256>>>(wout);
    attn_mma<<<dim3(N_ / 128, BH_), 256, attn_smem>>>();

    gemm_mma<0><<<gp, 256, gemm_smem>>>(ah, al, wth + 3*wN, wtl + 3*wN, bo, xout, nullptr, nullptr);
}